// round 6
// baseline (speedup 1.0000x reference)
#include <cuda_runtime.h>
#include <cuda_fp16.h>
#include <cstdint>
#include <cstddef>

// Problem constants
#define B_   16
#define N_   2048
#define E_   32768
#define D_   256
#define R_   8
#define L_   2

#define M_TOT (B_ * N_)       // 32768 rows
#define KDIM  256             // GEMM K = D
#define NOUT  2304            // R*D relation cols + D root cols
#define KT2   32              // K per stage
#define NT2   (KDIM / KT2)    // 8 stages
#define NBLK  9               // 8 relation col-blocks + 1 root col-block

// ---------------- scratch (device globals; no allocation allowed) ----------
__device__ float g_x[M_TOT * D_];                    // gathered embeddings
__device__ float g_y[M_TOT * D_];                    // layer-0 output
__device__ __half g_xw[(size_t)M_TOT * (R_ * D_)];   // 134 MB fp16 messages
__device__ float g_invdeg[M_TOT];
// pre-converted, pre-swizzled fp16 B tiles: [kt(8)*9+bx] x 16384 bytes
__device__ uint8_t g_Bh[NT2 * NBLK * 16384];

// ---------------- smem geometry for the GEMM -------------------------------
#define A_STRIDE  80                       // bytes per 32-fp16 A row (64B + 16 pad)
#define SA_BYTES  (128 * A_STRIDE)         // 10240 per A split
#define OFF_ALO   SA_BYTES                 // 10240
#define OFF_B     (2 * SA_BYTES)           // 20480 (128B aligned)
#define STAGE     (OFF_B + 16384)          // 36864
#define SMEM_DYN  (2 * STAGE + 128)        // 73856 (also >= 64KB staging + pad)

// ---------------- PTX helpers ----------------------------------------------
__device__ __forceinline__ uint32_t smem_u32(const void* p) {
    uint32_t a;
    asm("{ .reg .u64 t; cvta.to.shared.u64 t, %1; cvt.u32.u64 %0, t; }"
        : "=r"(a) : "l"(p));
    return a;
}
__device__ __forceinline__ void ldsm4(uint32_t (&r)[4], uint32_t addr) {
    asm volatile("ldmatrix.sync.aligned.m8n8.x4.shared.b16 {%0,%1,%2,%3}, [%4];"
                 : "=r"(r[0]), "=r"(r[1]), "=r"(r[2]), "=r"(r[3]) : "r"(addr));
}
__device__ __forceinline__ void ldsm4t(uint32_t (&r)[4], uint32_t addr) {
    asm volatile("ldmatrix.sync.aligned.m8n8.x4.trans.shared.b16 {%0,%1,%2,%3}, [%4];"
                 : "=r"(r[0]), "=r"(r[1]), "=r"(r[2]), "=r"(r[3]) : "r"(addr));
}
__device__ __forceinline__ void mma16816h(float (&c)[4], const uint32_t (&a)[4],
                                          uint32_t b0, uint32_t b1) {
    asm volatile("mma.sync.aligned.m16n8k16.row.col.f32.f16.f16.f32 "
                 "{%0,%1,%2,%3}, {%4,%5,%6,%7}, {%8,%9}, {%0,%1,%2,%3};"
                 : "+f"(c[0]), "+f"(c[1]), "+f"(c[2]), "+f"(c[3])
                 : "r"(a[0]), "r"(a[1]), "r"(a[2]), "r"(a[3]), "r"(b0), "r"(b1));
}
__device__ __forceinline__ void cp16(uint32_t dst, const void* src) {
    asm volatile("cp.async.cg.shared.global [%0], [%1], 16;"
                 :: "r"(dst), "l"(src) : "memory");
}
__device__ __forceinline__ void sts16(uint32_t addr, uint32_t a, uint32_t b,
                                      uint32_t c, uint32_t d) {
    asm volatile("st.shared.v4.b32 [%0], {%1, %2, %3, %4};"
                 :: "r"(addr), "r"(a), "r"(b), "r"(c), "r"(d) : "memory");
}
__device__ __forceinline__ void sts4(uint32_t addr, uint32_t v) {
    asm volatile("st.shared.b32 [%0], %1;" :: "r"(addr), "r"(v) : "memory");
}
__device__ __forceinline__ void lds16(uint4& v, uint32_t addr) {
    asm volatile("ld.shared.v4.b32 {%0, %1, %2, %3}, [%4];"
                 : "=r"(v.x), "=r"(v.y), "=r"(v.z), "=r"(v.w) : "r"(addr));
}
// split fp32 pair -> fp16 hi pair + fp16 lo pair (packed)
__device__ __forceinline__ void split2h(float x0, float x1, uint32_t& h, uint32_t& l) {
    __half2 hh = __floats2half2_rn(x0, x1);
    h = *(uint32_t*)&hh;
    float2 hf = __half22float2(hh);
    __half2 ll = __floats2half2_rn(x0 - hf.x, x1 - hf.y);
    l = *(uint32_t*)&ll;
}
__device__ __forceinline__ uint32_t cvt2h(float x0, float x1) {
    __half2 hh = __floats2half2_rn(x0, x1);
    return *(uint32_t*)&hh;
}

// ---------------- simple kernels --------------------------------------------
__global__ void gather_kernel(const int* __restrict__ nodes,
                              const float* __restrict__ emb,
                              float* __restrict__ x) {
    int idx = blockIdx.x * blockDim.x + threadIdx.x;
    if (idx >= M_TOT * (D_ / 4)) return;
    int node = idx >> 6;
    int q = idx & 63;
    int v = nodes[node];
    ((float4*)x)[idx] = ((const float4*)emb)[(size_t)v * 64 + q];
}

__global__ void zero_deg() {
    int idx = blockIdx.x * blockDim.x + threadIdx.x;
    if (idx < M_TOT) g_invdeg[idx] = 0.f;
}
__global__ void count_deg(const int* __restrict__ edges) {
    int idx = blockIdx.x * blockDim.x + threadIdx.x;
    if (idx >= B_ * E_) return;
    int b = idx >> 15;
    int e = idx & (E_ - 1);
    int dst = edges[(size_t)b * 2 * E_ + E_ + e];
    atomicAdd(&g_invdeg[b * N_ + dst], 1.0f);
}
__global__ void finalize_deg() {
    int idx = blockIdx.x * blockDim.x + threadIdx.x;
    if (idx < M_TOT) g_invdeg[idx] = 1.0f / fmaxf(g_invdeg[idx], 1.0f);
}

// Pre-convert + pre-swizzle W into ldmatrix-ready fp16 tile images.
// Logical B[k][n] = (n < 2048) ? W[n>>8][k][n&255] : Wroot[k][n-2048]
// Tile (kt, bx) image: [krow 0..31][granule g 0..31], row stride 512B,
//   byte_off = krow*512 + ((g ^ (krow & 7)) * 16), granule g covers n = bx*256+g*8..+7
__global__ void bconv_kernel(const float* __restrict__ Wl,
                             const float* __restrict__ Wr) {
    int gid = blockIdx.x * blockDim.x + threadIdx.x;   // NT2*NBLK*1024
    if (gid >= NT2 * NBLK * 1024) return;
    int tile = gid >> 10;           // kt*9 + bx
    int rem = gid & 1023;
    int krow = rem >> 5;
    int gq = rem & 31;
    int kt = tile / NBLK;
    int bx = tile - kt * NBLK;
    int k = kt * KT2 + krow;
    int n0 = bx * 256 + gq * 8;
    const float* src = (n0 < 2048)
        ? Wl + ((size_t)(n0 >> 8) << 16) + (size_t)k * 256 + (n0 & 255)
        : Wr + (size_t)k * 256 + (n0 - 2048);
    float4 v0 = ((const float4*)src)[0];
    float4 v1 = ((const float4*)src)[1];
    uint4 h;
    h.x = cvt2h(v0.x, v0.y);
    h.y = cvt2h(v0.z, v0.w);
    h.z = cvt2h(v1.x, v1.y);
    h.w = cvt2h(v1.z, v1.w);
    uint32_t off = (uint32_t)tile * 16384u + (uint32_t)krow * 512u +
                   ((uint32_t)(gq ^ (krow & 7)) << 4);
    *(uint4*)(g_Bh + off) = h;
}

// Scatter: per edge (one warp): Y[dst] += xw[etype, src, :] * invdeg[dst]
__global__ void scatter_kernel(const __half* __restrict__ xw,
                               const int* __restrict__ edges,
                               const int* __restrict__ types,
                               float* __restrict__ Y) {
    int gtid = blockIdx.x * blockDim.x + threadIdx.x;
    int w = gtid >> 5;
    int lane = gtid & 31;
    if (w >= B_ * E_) return;
    int b = w >> 15;
    int e = w & (E_ - 1);
    const int* eb = edges + (size_t)b * 2 * E_;
    int src = eb[e];
    int dst = eb[E_ + e];
    int r = types[(size_t)b * E_ + e];
    float idg = g_invdeg[b * N_ + dst];

    const uint4* row = (const uint4*)(xw + ((size_t)(b * N_ + src)) * (R_ * D_) +
                                      r * D_);
    uint4 v = row[lane];              // 16B = 8 halves
    const __half2* hp = (const __half2*)&v;
    float2 f0 = __half22float2(hp[0]);
    float2 f1 = __half22float2(hp[1]);
    float2 f2 = __half22float2(hp[2]);
    float2 f3 = __half22float2(hp[3]);
    float* yp = Y + (size_t)(b * N_ + dst) * D_ + lane * 8;
    asm volatile("red.global.add.v4.f32 [%0], {%1, %2, %3, %4};"
                 :: "l"(yp), "f"(f0.x * idg), "f"(f0.y * idg),
                    "f"(f1.x * idg), "f"(f1.y * idg) : "memory");
    asm volatile("red.global.add.v4.f32 [%0], {%1, %2, %3, %4};"
                 :: "l"(yp + 4), "f"(f2.x * idg), "f"(f2.y * idg),
                    "f"(f3.x * idg), "f"(f3.y * idg) : "memory");
}

// ---------------- warp-MMA GEMM ----------------------------------------------
// CTA: 128 rows x 256 cols of xw = [relu?](x) @ [W_cat | W_root].
// grid (9, 256): bx<8 -> write fp16 to g_xw (smem-staged); bx==8 -> Y = . + bias (fp32)
__global__ void __launch_bounds__(512, 1)
rgcn_gemm_mma(const float* __restrict__ X,
              const float* __restrict__ bias,
              float* __restrict__ Y,
              __half* __restrict__ XW,
              int relu_a) {
    extern __shared__ uint8_t smem_raw[];
    const uint32_t sbase = (smem_u32(smem_raw) + 127u) & ~127u;

    const int tid = threadIdx.x;
    const int lane = tid & 31;
    const int wid = tid >> 5;
    const int warp_m = wid & 3;      // 4 warps along M (32 rows each)
    const int warp_n = wid >> 2;     // 4 warps along N (64 cols each)
    const int bx = blockIdx.x;
    const int m0 = blockIdx.y * 128;

    // A fill mapping: 4 threads per row, 8 k-values each
    const int arow = tid >> 2;
    const int akb = (tid & 3) * 8;
    const uint32_t a_sts = (uint32_t)arow * A_STRIDE + (uint32_t)akb * 2;

    const int g = lane >> 2;
    const int tc = lane & 3;

    // ldmatrix address pieces
    uint32_t a_off[2];
#pragma unroll
    for (int mt = 0; mt < 2; mt++)
        a_off[mt] = (uint32_t)(warp_m * 32 + mt * 16 + (lane & 15)) * A_STRIDE +
                    (uint32_t)((lane >> 4) * 16);
    const uint32_t krow_base = (uint32_t)((lane & 7) + ((lane >> 3) & 1) * 8);
    uint32_t gg[4];
#pragma unroll
    for (int nt2 = 0; nt2 < 4; nt2++)
        gg[nt2] = (uint32_t)(((warp_n * 8 + nt2 * 2 + (lane >> 4)) ^ (lane & 7)) << 4);

    float c[2][8][4];
#pragma unroll
    for (int mt = 0; mt < 2; mt++)
#pragma unroll
        for (int nt = 0; nt < 8; nt++)
#pragma unroll
            for (int j = 0; j < 4; j++) c[mt][nt][j] = 0.f;

    float areg[8];   // prefetched fp32 A values for the NEXT stage

    auto issue_loads = [&](int kt, int s) {
        const uint32_t st = sbase + (uint32_t)s * STAGE;
        const uint8_t* bh = g_Bh + (size_t)(kt * NBLK + bx) * 16384 + tid * 16;
        cp16(st + OFF_B + tid * 16, bh);
        cp16(st + OFF_B + 8192 + tid * 16, bh + 8192);
        asm volatile("cp.async.commit_group;" ::: "memory");
        const float* asrc = X + (size_t)(m0 + arow) * KDIM + kt * KT2 + akb;
        float4 v0 = ((const float4*)asrc)[0];
        float4 v1 = ((const float4*)asrc)[1];
        areg[0] = v0.x; areg[1] = v0.y; areg[2] = v0.z; areg[3] = v0.w;
        areg[4] = v1.x; areg[5] = v1.y; areg[6] = v1.z; areg[7] = v1.w;
    };

    auto store_a = [&](int s) {
        const uint32_t st = sbase + (uint32_t)s * STAGE;
        if (relu_a) {
#pragma unroll
            for (int q = 0; q < 8; q++) areg[q] = fmaxf(areg[q], 0.f);
        }
        uint32_t hi[4], lo[4];
#pragma unroll
        for (int q = 0; q < 4; q++)
            split2h(areg[2 * q], areg[2 * q + 1], hi[q], lo[q]);
        uint32_t ad = st + a_sts;
        sts16(ad, hi[0], hi[1], hi[2], hi[3]);
        sts16(ad + OFF_ALO, lo[0], lo[1], lo[2], lo[3]);
    };

    auto compute = [&](int s) {
        const uint32_t st = sbase + (uint32_t)s * STAGE;
#pragma unroll
        for (int k16 = 0; k16 < 2; k16++) {
            const uint32_t kb2 = (uint32_t)(k16 * 32);
            const uint32_t brow = (uint32_t)((k16 * 16) + krow_base) * 512u;
            uint32_t ah[2][4], al[2][4], bb[4][4];
            ldsm4(ah[0], st + a_off[0] + kb2);
            ldsm4(ah[1], st + a_off[1] + kb2);
            ldsm4(al[0], st + OFF_ALO + a_off[0] + kb2);
            ldsm4(al[1], st + OFF_ALO + a_off[1] + kb2);
#pragma unroll
            for (int nt2 = 0; nt2 < 4; nt2++)
                ldsm4t(bb[nt2], st + OFF_B + brow + gg[nt2]);
#pragma unroll
            for (int mt = 0; mt < 2; mt++)
#pragma unroll
                for (int nt = 0; nt < 8; nt++)
                    mma16816h(c[mt][nt], ah[mt], bb[nt >> 1][(nt & 1) * 2],
                              bb[nt >> 1][(nt & 1) * 2 + 1]);
#pragma unroll
            for (int mt = 0; mt < 2; mt++)
#pragma unroll
                for (int nt = 0; nt < 8; nt++)
                    mma16816h(c[mt][nt], al[mt], bb[nt >> 1][(nt & 1) * 2],
                              bb[nt >> 1][(nt & 1) * 2 + 1]);
        }
    };

    issue_loads(0, 0);
    store_a(0);
    asm volatile("cp.async.wait_group 0;" ::: "memory");
    __syncthreads();

#pragma unroll 1
    for (int kt = 0; kt < NT2; kt++) {
        const int s = kt & 1;
        if (kt + 1 < NT2) issue_loads(kt + 1, s ^ 1);
        compute(s);
        if (kt + 1 < NT2) {
            store_a(s ^ 1);
            asm volatile("cp.async.wait_group 0;" ::: "memory");
            __syncthreads();
        }
    }

    if (bx == 8) {
        // root block: Y = c + bias (fp32)
#pragma unroll
        for (int mt = 0; mt < 2; mt++) {
            const int row = m0 + warp_m * 32 + mt * 16 + g;
#pragma unroll
            for (int nt = 0; nt < 8; nt++) {
                const int col = warp_n * 64 + nt * 8 + tc * 2;
                const float b0 = bias[col];
                const float b1 = bias[col + 1];
                *(float2*)&Y[(size_t)row * D_ + col] =
                    make_float2(c[mt][nt][0] + b0, c[mt][nt][1] + b1);
                *(float2*)&Y[(size_t)(row + 8) * D_ + col] =
                    make_float2(c[mt][nt][2] + b0, c[mt][nt][3] + b1);
            }
        }
    } else {
        // relation block: convert to fp16, stage via smem, coalesced store to XW
        __syncthreads();   // all warps done reading stage buffers
#pragma unroll
        for (int mt = 0; mt < 2; mt++) {
#pragma unroll
            for (int h = 0; h < 2; h++) {
                int lrow = warp_m * 32 + mt * 16 + h * 8 + g;
#pragma unroll
                for (int nt = 0; nt < 8; nt++) {
                    int gran = warp_n * 8 + nt;
                    uint32_t off = (uint32_t)lrow * 512 +
                                   ((uint32_t)(gran ^ (lrow & 7)) << 4) + tc * 4;
                    sts4(sbase + off, cvt2h(c[mt][nt][h * 2], c[mt][nt][h * 2 + 1]));
                }
            }
        }
        __syncthreads();
        __half* dst = XW + (size_t)m0 * (R_ * D_) + bx * D_;
#pragma unroll
        for (int p = 0; p < 8; p++) {
            int i = tid + p * 512;          // 4096 16B-chunks
            int row = i >> 5;
            int gran = i & 31;
            uint32_t soff = (uint32_t)row * 512 +
                            ((uint32_t)(gran ^ (row & 7)) << 4);
            uint4 v;
            lds16(v, sbase + soff);
            *(uint4*)(dst + (size_t)row * (R_ * D_) + gran * 8) = v;
        }
    }
}

// ---------------- launch ----------------------------------------------------
extern "C" void kernel_launch(void* const* d_in, const int* in_sizes, int n_in,
                              void* d_out, int out_size) {
    const int*   nodes = (const int*)d_in[0];
    const int*   edges = (const int*)d_in[1];
    const int*   types = (const int*)d_in[2];
    const float* emb   = (const float*)d_in[3];
    const float* W     = (const float*)d_in[4];
    const float* Wroot = (const float*)d_in[5];
    const float* bias  = (const float*)d_in[6];
    float* out = (float*)d_out;

    cudaFuncSetAttribute(rgcn_gemm_mma,
                         cudaFuncAttributeMaxDynamicSharedMemorySize, SMEM_DYN);

    float *x0 = nullptr, *y0 = nullptr;
    __half* xw = nullptr;
    cudaGetSymbolAddress((void**)&x0, g_x);
    cudaGetSymbolAddress((void**)&y0, g_y);
    cudaGetSymbolAddress((void**)&xw, g_xw);

    gather_kernel<<<(M_TOT * (D_ / 4) + 255) / 256, 256>>>(nodes, emb, x0);
    zero_deg<<<M_TOT / 256, 256>>>();
    count_deg<<<(B_ * E_) / 256, 256>>>(edges);
    finalize_deg<<<M_TOT / 256, 256>>>();

    const float* xin = x0;
    for (int l = 0; l < L_; l++) {
        bconv_kernel<<<(NT2 * NBLK * 1024 + 255) / 256, 256>>>(
            W + (size_t)l * R_ * D_ * D_, Wroot + (size_t)l * D_ * D_);
        float* Yl = (l == L_ - 1) ? out : y0;
        dim3 grid(NBLK, M_TOT / 128);   // (9, 256)
        rgcn_gemm_mma<<<grid, 512, SMEM_DYN>>>(
            xin, bias + (size_t)l * D_, Yl, xw, (l > 0) ? 1 : 0);
        scatter_kernel<<<(B_ * E_ * 32) / 256, 256>>>(xw, edges, types, Yl);
        xin = Yl;
    }
}

// round 7
// speedup vs baseline: 1.2703x; 1.2703x over previous
#include <cuda_runtime.h>
#include <cuda_fp16.h>
#include <cstdint>
#include <cstddef>

// Problem constants
#define B_   16
#define N_   2048
#define E_   32768
#define D_   256
#define R_   8
#define L_   2

#define M_TOT (B_ * N_)       // 32768 rows
#define KDIM  256             // GEMM K = D
#define KT2   32              // K per stage
#define NT2   (KDIM / KT2)    // 8 stages
#define NBLK  9               // 8 relation col-blocks + 1 root col-block

// ---------------- scratch (device globals; no allocation allowed) ----------
__device__ float g_x[M_TOT * D_];                    // gathered embeddings
__device__ float g_y[M_TOT * D_];                    // layer-0 output
__device__ __half g_xw[(size_t)M_TOT * (R_ * D_)];   // 134 MB fp16 messages
// CSR by destination (built once; edges are layer-invariant)
__device__ int g_degi[M_TOT];
__device__ int g_fill[M_TOT];
__device__ int g_rowptr[M_TOT + 1];
__device__ int g_adj[B_ * E_];                       // (r<<15) | src_global
// pre-converted, pre-swizzled fp16 B tiles: [kt(8)*9+bx] x 16384 bytes
__device__ uint8_t g_Bh[NT2 * NBLK * 16384];

// ---------------- smem geometry for the GEMM -------------------------------
#define A_STRIDE  80                       // bytes per 32-fp16 A row (64B + 16 pad)
#define SA_BYTES  (128 * A_STRIDE)         // 10240 per A split
#define OFF_ALO   SA_BYTES                 // 10240
#define OFF_B     (2 * SA_BYTES)           // 20480 (128B aligned)
#define STAGE     (OFF_B + 16384)          // 36864
#define SMEM_DYN  (2 * STAGE + 128)        // 73856 (also >= 64KB staging + pad)

// ---------------- PTX helpers ----------------------------------------------
__device__ __forceinline__ uint32_t smem_u32(const void* p) {
    uint32_t a;
    asm("{ .reg .u64 t; cvta.to.shared.u64 t, %1; cvt.u32.u64 %0, t; }"
        : "=r"(a) : "l"(p));
    return a;
}
__device__ __forceinline__ void ldsm4(uint32_t (&r)[4], uint32_t addr) {
    asm volatile("ldmatrix.sync.aligned.m8n8.x4.shared.b16 {%0,%1,%2,%3}, [%4];"
                 : "=r"(r[0]), "=r"(r[1]), "=r"(r[2]), "=r"(r[3]) : "r"(addr));
}
__device__ __forceinline__ void ldsm4t(uint32_t (&r)[4], uint32_t addr) {
    asm volatile("ldmatrix.sync.aligned.m8n8.x4.trans.shared.b16 {%0,%1,%2,%3}, [%4];"
                 : "=r"(r[0]), "=r"(r[1]), "=r"(r[2]), "=r"(r[3]) : "r"(addr));
}
__device__ __forceinline__ void mma16816h(float (&c)[4], const uint32_t (&a)[4],
                                          uint32_t b0, uint32_t b1) {
    asm volatile("mma.sync.aligned.m16n8k16.row.col.f32.f16.f16.f32 "
                 "{%0,%1,%2,%3}, {%4,%5,%6,%7}, {%8,%9}, {%0,%1,%2,%3};"
                 : "+f"(c[0]), "+f"(c[1]), "+f"(c[2]), "+f"(c[3])
                 : "r"(a[0]), "r"(a[1]), "r"(a[2]), "r"(a[3]), "r"(b0), "r"(b1));
}
__device__ __forceinline__ void cp16(uint32_t dst, const void* src) {
    asm volatile("cp.async.cg.shared.global [%0], [%1], 16;"
                 :: "r"(dst), "l"(src) : "memory");
}
__device__ __forceinline__ void sts16(uint32_t addr, uint32_t a, uint32_t b,
                                      uint32_t c, uint32_t d) {
    asm volatile("st.shared.v4.b32 [%0], {%1, %2, %3, %4};"
                 :: "r"(addr), "r"(a), "r"(b), "r"(c), "r"(d) : "memory");
}
__device__ __forceinline__ void sts4(uint32_t addr, uint32_t v) {
    asm volatile("st.shared.b32 [%0], %1;" :: "r"(addr), "r"(v) : "memory");
}
__device__ __forceinline__ void lds16(uint4& v, uint32_t addr) {
    asm volatile("ld.shared.v4.b32 {%0, %1, %2, %3}, [%4];"
                 : "=r"(v.x), "=r"(v.y), "=r"(v.z), "=r"(v.w) : "r"(addr));
}
// split fp32 pair -> fp16 hi pair + fp16 lo pair (packed)
__device__ __forceinline__ void split2h(float x0, float x1, uint32_t& h, uint32_t& l) {
    __half2 hh = __floats2half2_rn(x0, x1);
    h = *(uint32_t*)&hh;
    float2 hf = __half22float2(hh);
    __half2 ll = __floats2half2_rn(x0 - hf.x, x1 - hf.y);
    l = *(uint32_t*)&ll;
}
__device__ __forceinline__ uint32_t cvt2h(float x0, float x1) {
    __half2 hh = __floats2half2_rn(x0, x1);
    return *(uint32_t*)&hh;
}

// ---------------- simple kernels --------------------------------------------
__global__ void gather_kernel(const int* __restrict__ nodes,
                              const float* __restrict__ emb,
                              float* __restrict__ x) {
    int idx = blockIdx.x * blockDim.x + threadIdx.x;
    if (idx >= M_TOT * (D_ / 4)) return;
    int node = idx >> 6;
    int q = idx & 63;
    int v = nodes[node];
    ((float4*)x)[idx] = ((const float4*)emb)[(size_t)v * 64 + q];
}

// ---------------- CSR build (once) ------------------------------------------
__global__ void zero_counts() {
    int idx = blockIdx.x * blockDim.x + threadIdx.x;
    if (idx < M_TOT) { g_degi[idx] = 0; g_fill[idx] = 0; }
}
__global__ void count_deg(const int* __restrict__ edges) {
    int idx = blockIdx.x * blockDim.x + threadIdx.x;
    if (idx >= B_ * E_) return;
    int b = idx >> 15;
    int e = idx & (E_ - 1);
    int dst = edges[(size_t)b * 2 * E_ + E_ + e];
    atomicAdd(&g_degi[b * N_ + dst], 1);
}
// single-CTA exclusive scan of g_degi (32768 = 1024 threads x 32 elems)
__global__ void __launch_bounds__(1024, 1) scan_kernel() {
    __shared__ int wsum[32];
    int t = threadIdx.x;
    int lane = t & 31, w = t >> 5;
    int base = t * 32;
    int local[32];
    int s = 0;
#pragma unroll
    for (int i = 0; i < 32; i++) { local[i] = s; s += g_degi[base + i]; }
    int v = s;
#pragma unroll
    for (int off = 1; off < 32; off <<= 1) {
        int u = __shfl_up_sync(0xFFFFFFFFu, v, off);
        if (lane >= off) v += u;
    }
    if (lane == 31) wsum[w] = v;
    __syncthreads();
    if (w == 0) {
        int x = wsum[lane];
#pragma unroll
        for (int off = 1; off < 32; off <<= 1) {
            int u = __shfl_up_sync(0xFFFFFFFFu, x, off);
            if (lane >= off) x += u;
        }
        wsum[lane] = x;
    }
    __syncthreads();
    int tp = (v - s) + (w > 0 ? wsum[w - 1] : 0);
#pragma unroll
    for (int i = 0; i < 32; i++) g_rowptr[base + i] = tp + local[i];
    if (t == 1023) g_rowptr[M_TOT] = tp + s;
}
__global__ void fill_adj(const int* __restrict__ edges,
                         const int* __restrict__ types) {
    int idx = blockIdx.x * blockDim.x + threadIdx.x;
    if (idx >= B_ * E_) return;
    int b = idx >> 15;
    int e = idx & (E_ - 1);
    const int* eb = edges + (size_t)b * 2 * E_;
    int src = eb[e];
    int dst = eb[E_ + e];
    int r = types[(size_t)b * E_ + e];
    int gdst = b * N_ + dst;
    int pos = g_rowptr[gdst] + atomicAdd(&g_fill[gdst], 1);
    g_adj[pos] = (r << 15) | (b * N_ + src);
}

// Pre-convert + pre-swizzle W into ldmatrix-ready fp16 tile images.
__global__ void bconv_kernel(const float* __restrict__ Wl,
                             const float* __restrict__ Wr) {
    int gid = blockIdx.x * blockDim.x + threadIdx.x;   // NT2*NBLK*1024
    if (gid >= NT2 * NBLK * 1024) return;
    int tile = gid >> 10;           // kt*9 + bx
    int rem = gid & 1023;
    int krow = rem >> 5;
    int gq = rem & 31;
    int kt = tile / NBLK;
    int bx = tile - kt * NBLK;
    int k = kt * KT2 + krow;
    int n0 = bx * 256 + gq * 8;
    const float* src = (n0 < 2048)
        ? Wl + ((size_t)(n0 >> 8) << 16) + (size_t)k * 256 + (n0 & 255)
        : Wr + (size_t)k * 256 + (n0 - 2048);
    float4 v0 = ((const float4*)src)[0];
    float4 v1 = ((const float4*)src)[1];
    uint4 h;
    h.x = cvt2h(v0.x, v0.y);
    h.y = cvt2h(v0.z, v0.w);
    h.z = cvt2h(v1.x, v1.y);
    h.w = cvt2h(v1.z, v1.w);
    uint32_t off = (uint32_t)tile * 16384u + (uint32_t)krow * 512u +
                   ((uint32_t)(gq ^ (krow & 7)) << 4);
    *(uint4*)(g_Bh + off) = h;
}

// ---------------- atomic-free aggregation ------------------------------------
// One warp per dst node: Y[dst] += (sum over in-edges of xw[src, r, :]) / max(deg,1)
__global__ void __launch_bounds__(256)
aggregate_kernel(const __half* __restrict__ xw, float* __restrict__ Y) {
    int w = (blockIdx.x * blockDim.x + threadIdx.x) >> 5;
    int lane = threadIdx.x & 31;
    if (w >= M_TOT) return;
    int beg = g_rowptr[w];
    int end = g_rowptr[w + 1];

    float acc[8] = {0.f, 0.f, 0.f, 0.f, 0.f, 0.f, 0.f, 0.f};
#pragma unroll 2
    for (int p = beg; p < end; p++) {
        int ent = g_adj[p];
        int srcg = ent & 32767;
        int r = ent >> 15;
        uint4 v = *((const uint4*)(xw + (size_t)srcg * (R_ * D_) + r * D_) + lane);
        const __half2* hp = (const __half2*)&v;
        float2 f0 = __half22float2(hp[0]);
        float2 f1 = __half22float2(hp[1]);
        float2 f2 = __half22float2(hp[2]);
        float2 f3 = __half22float2(hp[3]);
        acc[0] += f0.x; acc[1] += f0.y; acc[2] += f1.x; acc[3] += f1.y;
        acc[4] += f2.x; acc[5] += f2.y; acc[6] += f3.x; acc[7] += f3.y;
    }
    float idg = 1.0f / (float)((end - beg) > 1 ? (end - beg) : 1);
    float* yp = Y + (size_t)w * D_ + lane * 8;
    float4 y0 = *(float4*)yp;
    float4 y1 = *(float4*)(yp + 4);
    y0.x += acc[0] * idg; y0.y += acc[1] * idg;
    y0.z += acc[2] * idg; y0.w += acc[3] * idg;
    y1.x += acc[4] * idg; y1.y += acc[5] * idg;
    y1.z += acc[6] * idg; y1.w += acc[7] * idg;
    *(float4*)yp = y0;
    *(float4*)(yp + 4) = y1;
}

// ---------------- warp-MMA GEMM ----------------------------------------------
// CTA: 128 rows x 256 cols of xw = [relu?](x) @ [W_cat | W_root].
// grid (9, 256): bx<8 -> write fp16 to g_xw (smem-staged); bx==8 -> Y = . + bias
__global__ void __launch_bounds__(512, 1)
rgcn_gemm_mma(const float* __restrict__ X,
              const float* __restrict__ bias,
              float* __restrict__ Y,
              __half* __restrict__ XW,
              int relu_a) {
    extern __shared__ uint8_t smem_raw[];
    const uint32_t sbase = (smem_u32(smem_raw) + 127u) & ~127u;

    const int tid = threadIdx.x;
    const int lane = tid & 31;
    const int wid = tid >> 5;
    const int warp_m = wid & 3;      // 4 warps along M (32 rows each)
    const int warp_n = wid >> 2;     // 4 warps along N (64 cols each)
    const int bx = blockIdx.x;
    const int m0 = blockIdx.y * 128;

    // A fill mapping: 4 threads per row, 8 k-values each
    const int arow = tid >> 2;
    const int akb = (tid & 3) * 8;
    const uint32_t a_sts = (uint32_t)arow * A_STRIDE + (uint32_t)akb * 2;

    const int g = lane >> 2;
    const int tc = lane & 3;

    // ldmatrix address pieces
    uint32_t a_off[2];
#pragma unroll
    for (int mt = 0; mt < 2; mt++)
        a_off[mt] = (uint32_t)(warp_m * 32 + mt * 16 + (lane & 15)) * A_STRIDE +
                    (uint32_t)((lane >> 4) * 16);
    const uint32_t krow_base = (uint32_t)((lane & 7) + ((lane >> 3) & 1) * 8);
    uint32_t gg[4];
#pragma unroll
    for (int nt2 = 0; nt2 < 4; nt2++)
        gg[nt2] = (uint32_t)(((warp_n * 8 + nt2 * 2 + (lane >> 4)) ^ (lane & 7)) << 4);

    float c[2][8][4];
#pragma unroll
    for (int mt = 0; mt < 2; mt++)
#pragma unroll
        for (int nt = 0; nt < 8; nt++)
#pragma unroll
            for (int j = 0; j < 4; j++) c[mt][nt][j] = 0.f;

    float areg[8];   // prefetched fp32 A values for the NEXT stage

    auto issue_loads = [&](int kt, int s) {
        const uint32_t st = sbase + (uint32_t)s * STAGE;
        const uint8_t* bh = g_Bh + (size_t)(kt * NBLK + bx) * 16384 + tid * 16;
        cp16(st + OFF_B + tid * 16, bh);
        cp16(st + OFF_B + 8192 + tid * 16, bh + 8192);
        asm volatile("cp.async.commit_group;" ::: "memory");
        const float* asrc = X + (size_t)(m0 + arow) * KDIM + kt * KT2 + akb;
        float4 v0 = ((const float4*)asrc)[0];
        float4 v1 = ((const float4*)asrc)[1];
        areg[0] = v0.x; areg[1] = v0.y; areg[2] = v0.z; areg[3] = v0.w;
        areg[4] = v1.x; areg[5] = v1.y; areg[6] = v1.z; areg[7] = v1.w;
    };

    auto store_a = [&](int s) {
        const uint32_t st = sbase + (uint32_t)s * STAGE;
        if (relu_a) {
#pragma unroll
            for (int q = 0; q < 8; q++) areg[q] = fmaxf(areg[q], 0.f);
        }
        uint32_t hi[4], lo[4];
#pragma unroll
        for (int q = 0; q < 4; q++)
            split2h(areg[2 * q], areg[2 * q + 1], hi[q], lo[q]);
        uint32_t ad = st + a_sts;
        sts16(ad, hi[0], hi[1], hi[2], hi[3]);
        sts16(ad + OFF_ALO, lo[0], lo[1], lo[2], lo[3]);
    };

    auto compute = [&](int s) {
        const uint32_t st = sbase + (uint32_t)s * STAGE;
#pragma unroll
        for (int k16 = 0; k16 < 2; k16++) {
            const uint32_t kb2 = (uint32_t)(k16 * 32);
            const uint32_t brow = (uint32_t)((k16 * 16) + krow_base) * 512u;
            uint32_t ah[2][4], al[2][4], bb[4][4];
            ldsm4(ah[0], st + a_off[0] + kb2);
            ldsm4(ah[1], st + a_off[1] + kb2);
            ldsm4(al[0], st + OFF_ALO + a_off[0] + kb2);
            ldsm4(al[1], st + OFF_ALO + a_off[1] + kb2);
#pragma unroll
            for (int nt2 = 0; nt2 < 4; nt2++)
                ldsm4t(bb[nt2], st + OFF_B + brow + gg[nt2]);
#pragma unroll
            for (int mt = 0; mt < 2; mt++)
#pragma unroll
                for (int nt = 0; nt < 8; nt++)
                    mma16816h(c[mt][nt], ah[mt], bb[nt >> 1][(nt & 1) * 2],
                              bb[nt >> 1][(nt & 1) * 2 + 1]);
#pragma unroll
            for (int mt = 0; mt < 2; mt++)
#pragma unroll
                for (int nt = 0; nt < 8; nt++)
                    mma16816h(c[mt][nt], al[mt], bb[nt >> 1][(nt & 1) * 2],
                              bb[nt >> 1][(nt & 1) * 2 + 1]);
        }
    };

    issue_loads(0, 0);
    store_a(0);
    asm volatile("cp.async.wait_group 0;" ::: "memory");
    __syncthreads();

#pragma unroll 1
    for (int kt = 0; kt < NT2; kt++) {
        const int s = kt & 1;
        if (kt + 1 < NT2) issue_loads(kt + 1, s ^ 1);
        compute(s);
        if (kt + 1 < NT2) {
            store_a(s ^ 1);
            asm volatile("cp.async.wait_group 0;" ::: "memory");
            __syncthreads();
        }
    }

    if (bx == 8) {
        // root block: Y = c + bias (fp32)
#pragma unroll
        for (int mt = 0; mt < 2; mt++) {
            const int row = m0 + warp_m * 32 + mt * 16 + g;
#pragma unroll
            for (int nt = 0; nt < 8; nt++) {
                const int col = warp_n * 64 + nt * 8 + tc * 2;
                const float b0 = bias[col];
                const float b1 = bias[col + 1];
                *(float2*)&Y[(size_t)row * D_ + col] =
                    make_float2(c[mt][nt][0] + b0, c[mt][nt][1] + b1);
                *(float2*)&Y[(size_t)(row + 8) * D_ + col] =
                    make_float2(c[mt][nt][2] + b0, c[mt][nt][3] + b1);
            }
        }
    } else {
        // relation block: convert to fp16, stage via smem, coalesced store to XW
        __syncthreads();   // all warps done reading stage buffers
#pragma unroll
        for (int mt = 0; mt < 2; mt++) {
#pragma unroll
            for (int h = 0; h < 2; h++) {
                int lrow = warp_m * 32 + mt * 16 + h * 8 + g;
#pragma unroll
                for (int nt = 0; nt < 8; nt++) {
                    int gran = warp_n * 8 + nt;
                    uint32_t off = (uint32_t)lrow * 512 +
                                   ((uint32_t)(gran ^ (lrow & 7)) << 4) + tc * 4;
                    sts4(sbase + off, cvt2h(c[mt][nt][h * 2], c[mt][nt][h * 2 + 1]));
                }
            }
        }
        __syncthreads();
        __half* dst = XW + (size_t)m0 * (R_ * D_) + bx * D_;
#pragma unroll
        for (int p = 0; p < 8; p++) {
            int i = tid + p * 512;          // 4096 16B-chunks
            int row = i >> 5;
            int gran = i & 31;
            uint32_t soff = (uint32_t)row * 512 +
                            ((uint32_t)(gran ^ (row & 7)) << 4);
            uint4 v;
            lds16(v, sbase + soff);
            *(uint4*)(dst + (size_t)row * (R_ * D_) + gran * 8) = v;
        }
    }
}

// ---------------- launch ----------------------------------------------------
extern "C" void kernel_launch(void* const* d_in, const int* in_sizes, int n_in,
                              void* d_out, int out_size) {
    const int*   nodes = (const int*)d_in[0];
    const int*   edges = (const int*)d_in[1];
    const int*   types = (const int*)d_in[2];
    const float* emb   = (const float*)d_in[3];
    const float* W     = (const float*)d_in[4];
    const float* Wroot = (const float*)d_in[5];
    const float* bias  = (const float*)d_in[6];
    float* out = (float*)d_out;

    cudaFuncSetAttribute(rgcn_gemm_mma,
                         cudaFuncAttributeMaxDynamicSharedMemorySize, SMEM_DYN);

    float *x0 = nullptr, *y0 = nullptr;
    __half* xw = nullptr;
    cudaGetSymbolAddress((void**)&x0, g_x);
    cudaGetSymbolAddress((void**)&y0, g_y);
    cudaGetSymbolAddress((void**)&xw, g_xw);

    gather_kernel<<<(M_TOT * (D_ / 4) + 255) / 256, 256>>>(nodes, emb, x0);

    // CSR build (once; edges are identical for both layers)
    zero_counts<<<M_TOT / 256, 256>>>();
    count_deg<<<(B_ * E_) / 256, 256>>>(edges);
    scan_kernel<<<1, 1024>>>();
    fill_adj<<<(B_ * E_) / 256, 256>>>(edges, types);

    const float* xin = x0;
    for (int l = 0; l < L_; l++) {
        bconv_kernel<<<(NT2 * NBLK * 1024 + 255) / 256, 256>>>(
            W + (size_t)l * R_ * D_ * D_, Wroot + (size_t)l * D_ * D_);
        float* Yl = (l == L_ - 1) ? out : y0;
        dim3 grid(NBLK, M_TOT / 128);   // (9, 256)
        rgcn_gemm_mma<<<grid, 512, SMEM_DYN>>>(
            xin, bias + (size_t)l * D_, Yl, xw, (l > 0) ? 1 : 0);
        aggregate_kernel<<<M_TOT / 8, 256>>>(xw, Yl);
        xin = Yl;
    }
}

// round 8
// speedup vs baseline: 1.3005x; 1.0237x over previous
#include <cuda_runtime.h>
#include <cuda_fp16.h>
#include <cstdint>
#include <cstddef>

// Problem constants
#define B_   16
#define N_   2048
#define E_   32768
#define D_   256
#define R_   8
#define L_   2

#define M_TOT (B_ * N_)       // 32768 rows
#define KDIM  256             // GEMM K = D
#define KT2   32              // K per stage
#define NT2   (KDIM / KT2)    // 8 stages
#define NBLK  9               // 8 relation col-blocks + 1 root col-block

// ---------------- scratch (device globals; no allocation allowed) ----------
__device__ float g_y[M_TOT * D_];                    // inter-layer output
__device__ __half g_xhi[M_TOT * D_];                 // pre-split A (hi)
__device__ __half g_xlo[M_TOT * D_];                 // pre-split A (lo)
__device__ __half g_xw[(size_t)M_TOT * (R_ * D_)];   // 134 MB fp16 messages
// CSR by destination (built once; edges are layer-invariant)
__device__ int g_degi[M_TOT];
__device__ int g_fill[M_TOT];
__device__ int g_rowptr[M_TOT + 1];
__device__ int g_bsum[128];
__device__ int g_adj[B_ * E_];                       // (r<<15) | src_global
// pre-converted, pre-swizzled fp16 B tiles: [kt(8)*9+bx] x 16384 bytes
__device__ uint8_t g_Bh[NT2 * NBLK * 16384];

// ---------------- smem geometry for the GEMM -------------------------------
#define A_STRIDE  80                       // bytes per 32-fp16 A row (64B + 16 pad)
#define SA_BYTES  (128 * A_STRIDE)         // 10240 per A split
#define OFF_ALO   SA_BYTES                 // 10240
#define OFF_B     (2 * SA_BYTES)           // 20480 (128B aligned)
#define STAGE     (OFF_B + 16384)          // 36864
#define NSTG      3
#define SMEM_DYN  (NSTG * STAGE + 128)     // 110720

// ---------------- PTX helpers ----------------------------------------------
__device__ __forceinline__ uint32_t smem_u32(const void* p) {
    uint32_t a;
    asm("{ .reg .u64 t; cvta.to.shared.u64 t, %1; cvt.u32.u64 %0, t; }"
        : "=r"(a) : "l"(p));
    return a;
}
__device__ __forceinline__ void ldsm4(uint32_t (&r)[4], uint32_t addr) {
    asm volatile("ldmatrix.sync.aligned.m8n8.x4.shared.b16 {%0,%1,%2,%3}, [%4];"
                 : "=r"(r[0]), "=r"(r[1]), "=r"(r[2]), "=r"(r[3]) : "r"(addr));
}
__device__ __forceinline__ void ldsm4t(uint32_t (&r)[4], uint32_t addr) {
    asm volatile("ldmatrix.sync.aligned.m8n8.x4.trans.shared.b16 {%0,%1,%2,%3}, [%4];"
                 : "=r"(r[0]), "=r"(r[1]), "=r"(r[2]), "=r"(r[3]) : "r"(addr));
}
__device__ __forceinline__ void mma16816h(float (&c)[4], const uint32_t (&a)[4],
                                          uint32_t b0, uint32_t b1) {
    asm volatile("mma.sync.aligned.m16n8k16.row.col.f32.f16.f16.f32 "
                 "{%0,%1,%2,%3}, {%4,%5,%6,%7}, {%8,%9}, {%0,%1,%2,%3};"
                 : "+f"(c[0]), "+f"(c[1]), "+f"(c[2]), "+f"(c[3])
                 : "r"(a[0]), "r"(a[1]), "r"(a[2]), "r"(a[3]), "r"(b0), "r"(b1));
}
__device__ __forceinline__ void cp16(uint32_t dst, const void* src) {
    asm volatile("cp.async.cg.shared.global [%0], [%1], 16;"
                 :: "r"(dst), "l"(src) : "memory");
}
__device__ __forceinline__ void sts4(uint32_t addr, uint32_t v) {
    asm volatile("st.shared.b32 [%0], %1;" :: "r"(addr), "r"(v) : "memory");
}
__device__ __forceinline__ void lds16(uint4& v, uint32_t addr) {
    asm volatile("ld.shared.v4.b32 {%0, %1, %2, %3}, [%4];"
                 : "=r"(v.x), "=r"(v.y), "=r"(v.z), "=r"(v.w) : "r"(addr));
}
// split fp32 pair -> fp16 hi pair + fp16 lo pair (packed)
__device__ __forceinline__ void split2h(float x0, float x1, uint32_t& h, uint32_t& l) {
    __half2 hh = __floats2half2_rn(x0, x1);
    h = *(uint32_t*)&hh;
    float2 hf = __half22float2(hh);
    __half2 ll = __floats2half2_rn(x0 - hf.x, x1 - hf.y);
    l = *(uint32_t*)&ll;
}
__device__ __forceinline__ uint32_t cvt2h(float x0, float x1) {
    __half2 hh = __floats2half2_rn(x0, x1);
    return *(uint32_t*)&hh;
}

// ---------------- A pre-split kernels ----------------------------------------
// layer 0: gather emb[nodes] and split to fp16 hi/lo (no intermediate fp32 x)
__global__ void asplit0_kernel(const int* __restrict__ nodes,
                               const float* __restrict__ emb) {
    int idx = blockIdx.x * blockDim.x + threadIdx.x;   // M_TOT*32
    if (idx >= M_TOT * 32) return;
    int node = idx >> 5;
    int q = idx & 31;
    int v = nodes[node];
    const float4* src = (const float4*)(emb + (size_t)v * D_ + q * 8);
    float4 a = src[0];
    float4 b = src[1];
    uint4 h, l;
    split2h(a.x, a.y, h.x, l.x);
    split2h(a.z, a.w, h.y, l.y);
    split2h(b.x, b.y, h.z, l.z);
    split2h(b.z, b.w, h.w, l.w);
    *((uint4*)(g_xhi) + idx) = h;
    *((uint4*)(g_xlo) + idx) = l;
}
// between layers: relu(Y) -> split
__global__ void asplit1_kernel(const float* __restrict__ Y) {
    int idx = blockIdx.x * blockDim.x + threadIdx.x;
    if (idx >= M_TOT * 32) return;
    const float4* src = (const float4*)Y + idx * 2;
    float4 a = src[0];
    float4 b = src[1];
    a.x = fmaxf(a.x, 0.f); a.y = fmaxf(a.y, 0.f);
    a.z = fmaxf(a.z, 0.f); a.w = fmaxf(a.w, 0.f);
    b.x = fmaxf(b.x, 0.f); b.y = fmaxf(b.y, 0.f);
    b.z = fmaxf(b.z, 0.f); b.w = fmaxf(b.w, 0.f);
    uint4 h, l;
    split2h(a.x, a.y, h.x, l.x);
    split2h(a.z, a.w, h.y, l.y);
    split2h(b.x, b.y, h.z, l.z);
    split2h(b.z, b.w, h.w, l.w);
    *((uint4*)(g_xhi) + idx) = h;
    *((uint4*)(g_xlo) + idx) = l;
}

// ---------------- CSR build (once) ------------------------------------------
__global__ void zero_counts() {
    int idx = blockIdx.x * blockDim.x + threadIdx.x;
    if (idx < M_TOT) { g_degi[idx] = 0; g_fill[idx] = 0; }
}
__global__ void count_deg(const int* __restrict__ edges) {
    int idx = blockIdx.x * blockDim.x + threadIdx.x;
    if (idx >= B_ * E_) return;
    int b = idx >> 15;
    int e = idx & (E_ - 1);
    int dst = edges[(size_t)b * 2 * E_ + E_ + e];
    atomicAdd(&g_degi[b * N_ + dst], 1);
}
// phase 1: per-256-block local exclusive scan + block sums (128 CTAs)
__global__ void scan1_kernel() {
    __shared__ int ws[8];
    int b = blockIdx.x, t = threadIdx.x, lane = t & 31, w = t >> 5;
    int i = b * 256 + t;
    int d = g_degi[i];
    int v = d;
#pragma unroll
    for (int off = 1; off < 32; off <<= 1) {
        int u = __shfl_up_sync(0xFFFFFFFFu, v, off);
        if (lane >= off) v += u;
    }
    if (lane == 31) ws[w] = v;
    __syncthreads();
    if (w == 0 && lane < 8) {
        int x = ws[lane];
#pragma unroll
        for (int off = 1; off < 8; off <<= 1) {
            int u = __shfl_up_sync(0xFFu, x, off);
            if (lane >= off) x += u;
        }
        ws[lane] = x;
    }
    __syncthreads();
    int incl = v + (w > 0 ? ws[w - 1] : 0);
    g_rowptr[i] = incl - d;
    if (t == 255) g_bsum[b] = incl;
}
// phase 2: scan the 128 block sums (1 CTA)
__global__ void scan2_kernel() {
    __shared__ int ws[4];
    int t = threadIdx.x, lane = t & 31, w = t >> 5;
    int d = g_bsum[t];
    int v = d;
#pragma unroll
    for (int off = 1; off < 32; off <<= 1) {
        int u = __shfl_up_sync(0xFFFFFFFFu, v, off);
        if (lane >= off) v += u;
    }
    if (lane == 31) ws[w] = v;
    __syncthreads();
    if (w == 0 && lane < 4) {
        int x = ws[lane];
#pragma unroll
        for (int off = 1; off < 4; off <<= 1) {
            int u = __shfl_up_sync(0xFu, x, off);
            if (lane >= off) x += u;
        }
        ws[lane] = x;
    }
    __syncthreads();
    int incl = v + (w > 0 ? ws[w - 1] : 0);
    g_bsum[t] = incl - d;                 // exclusive block offset
    if (t == 127) g_rowptr[M_TOT] = incl; // total (= B_*E_)
}
// phase 3: add block offsets
__global__ void scan3_kernel() {
    int i = blockIdx.x * blockDim.x + threadIdx.x;
    g_rowptr[i] += g_bsum[blockIdx.x];
}
__global__ void fill_adj(const int* __restrict__ edges,
                         const int* __restrict__ types) {
    int idx = blockIdx.x * blockDim.x + threadIdx.x;
    if (idx >= B_ * E_) return;
    int b = idx >> 15;
    int e = idx & (E_ - 1);
    const int* eb = edges + (size_t)b * 2 * E_;
    int src = eb[e];
    int dst = eb[E_ + e];
    int r = types[(size_t)b * E_ + e];
    int gdst = b * N_ + dst;
    int pos = g_rowptr[gdst] + atomicAdd(&g_fill[gdst], 1);
    g_adj[pos] = (r << 15) | (b * N_ + src);
}

// Pre-convert + pre-swizzle W into ldmatrix-ready fp16 tile images.
__global__ void bconv_kernel(const float* __restrict__ Wl,
                             const float* __restrict__ Wr) {
    int gid = blockIdx.x * blockDim.x + threadIdx.x;   // NT2*NBLK*1024
    if (gid >= NT2 * NBLK * 1024) return;
    int tile = gid >> 10;           // kt*9 + bx
    int rem = gid & 1023;
    int krow = rem >> 5;
    int gq = rem & 31;
    int kt = tile / NBLK;
    int bx = tile - kt * NBLK;
    int k = kt * KT2 + krow;
    int n0 = bx * 256 + gq * 8;
    const float* src = (n0 < 2048)
        ? Wl + ((size_t)(n0 >> 8) << 16) + (size_t)k * 256 + (n0 & 255)
        : Wr + (size_t)k * 256 + (n0 - 2048);
    float4 v0 = ((const float4*)src)[0];
    float4 v1 = ((const float4*)src)[1];
    uint4 h;
    h.x = cvt2h(v0.x, v0.y);
    h.y = cvt2h(v0.z, v0.w);
    h.z = cvt2h(v1.x, v1.y);
    h.w = cvt2h(v1.z, v1.w);
    uint32_t off = (uint32_t)tile * 16384u + (uint32_t)krow * 512u +
                   ((uint32_t)(gq ^ (krow & 7)) << 4);
    *(uint4*)(g_Bh + off) = h;
}

// ---------------- atomic-free aggregation ------------------------------------
// One warp per dst node: Y[dst] += (sum over in-edges of xw[src, r, :]) / max(deg,1)
__global__ void __launch_bounds__(256)
aggregate_kernel(const __half* __restrict__ xw, float* __restrict__ Y) {
    int w = (blockIdx.x * blockDim.x + threadIdx.x) >> 5;
    int lane = threadIdx.x & 31;
    if (w >= M_TOT) return;
    int beg = g_rowptr[w];
    int end = g_rowptr[w + 1];

    float acc[8] = {0.f, 0.f, 0.f, 0.f, 0.f, 0.f, 0.f, 0.f};
    int p = beg;
    for (; p + 2 <= end; p += 2) {
        int e0 = g_adj[p];
        int e1 = g_adj[p + 1];
        uint4 v0 = *((const uint4*)(xw + ((size_t)(e0 & 32767) * R_ + (e0 >> 15)) * D_) + lane);
        uint4 v1 = *((const uint4*)(xw + ((size_t)(e1 & 32767) * R_ + (e1 >> 15)) * D_) + lane);
        const __half2* h0 = (const __half2*)&v0;
        const __half2* h1 = (const __half2*)&v1;
#pragma unroll
        for (int j = 0; j < 4; j++) {
            float2 f0 = __half22float2(h0[j]);
            float2 f1 = __half22float2(h1[j]);
            acc[2 * j] += f0.x + f1.x;
            acc[2 * j + 1] += f0.y + f1.y;
        }
    }
    if (p < end) {
        int e0 = g_adj[p];
        uint4 v0 = *((const uint4*)(xw + ((size_t)(e0 & 32767) * R_ + (e0 >> 15)) * D_) + lane);
        const __half2* h0 = (const __half2*)&v0;
#pragma unroll
        for (int j = 0; j < 4; j++) {
            float2 f0 = __half22float2(h0[j]);
            acc[2 * j] += f0.x;
            acc[2 * j + 1] += f0.y;
        }
    }
    float idg = 1.0f / (float)((end - beg) > 1 ? (end - beg) : 1);
    float* yp = Y + (size_t)w * D_ + lane * 8;
    float4 y0 = *(float4*)yp;
    float4 y1 = *(float4*)(yp + 4);
    y0.x += acc[0] * idg; y0.y += acc[1] * idg;
    y0.z += acc[2] * idg; y0.w += acc[3] * idg;
    y1.x += acc[4] * idg; y1.y += acc[5] * idg;
    y1.z += acc[6] * idg; y1.w += acc[7] * idg;
    *(float4*)yp = y0;
    *(float4*)(yp + 4) = y1;
}

// ---------------- warp-MMA GEMM ----------------------------------------------
// CTA: 128 rows x 256 cols of xw = Xsplit @ [W_cat | W_root].
// A pre-split in gmem (fp16 hi/lo) -> all stage feeding is pure cp.async.
// grid (9, 256): bx<8 -> fp16 to g_xw (smem-staged); bx==8 -> Y = . + bias
__global__ void __launch_bounds__(512, 1)
rgcn_gemm_mma(const __half* __restrict__ Xhi,
              const __half* __restrict__ Xlo,
              const float* __restrict__ bias,
              float* __restrict__ Y,
              __half* __restrict__ XW) {
    extern __shared__ uint8_t smem_raw[];
    const uint32_t sbase = (smem_u32(smem_raw) + 127u) & ~127u;

    const int tid = threadIdx.x;
    const int lane = tid & 31;
    const int wid = tid >> 5;
    const int warp_m = wid & 3;      // 4 warps along M (32 rows each)
    const int warp_n = wid >> 2;     // 4 warps along N (64 cols each)
    const int bx = blockIdx.x;
    const int m0 = blockIdx.y * 128;

    // A fill mapping: 4 threads per row, one 16B chunk (8 halves) each
    const int arow = tid >> 2;
    const int ac = tid & 3;
    const uint32_t a_sts = (uint32_t)arow * A_STRIDE + (uint32_t)ac * 16;
    const size_t a_goff = (size_t)(m0 + arow) * KDIM + ac * 8;

    const int g = lane >> 2;
    const int tc = lane & 3;

    // ldmatrix address pieces
    uint32_t a_off[2];
#pragma unroll
    for (int mt = 0; mt < 2; mt++)
        a_off[mt] = (uint32_t)(warp_m * 32 + mt * 16 + (lane & 15)) * A_STRIDE +
                    (uint32_t)((lane >> 4) * 16);
    const uint32_t krow_base = (uint32_t)((lane & 7) + ((lane >> 3) & 1) * 8);
    uint32_t gg[4];
#pragma unroll
    for (int nt2 = 0; nt2 < 4; nt2++)
        gg[nt2] = (uint32_t)(((warp_n * 8 + nt2 * 2 + (lane >> 4)) ^ (lane & 7)) << 4);

    float c[2][8][4];
#pragma unroll
    for (int mt = 0; mt < 2; mt++)
#pragma unroll
        for (int nt = 0; nt < 8; nt++)
#pragma unroll
            for (int j = 0; j < 4; j++) c[mt][nt][j] = 0.f;

    auto issue_loads = [&](int kt, int s) {
        const uint32_t st = sbase + (uint32_t)s * STAGE;
        const uint8_t* bh = g_Bh + (size_t)(kt * NBLK + bx) * 16384 + tid * 16;
        cp16(st + OFF_B + tid * 16, bh);
        cp16(st + OFF_B + 8192 + tid * 16, bh + 8192);
        cp16(st + a_sts, Xhi + a_goff + kt * KT2);
        cp16(st + OFF_ALO + a_sts, Xlo + a_goff + kt * KT2);
        asm volatile("cp.async.commit_group;" ::: "memory");
    };

    auto compute = [&](int s) {
        const uint32_t st = sbase + (uint32_t)s * STAGE;
#pragma unroll
        for (int k16 = 0; k16 < 2; k16++) {
            const uint32_t kb2 = (uint32_t)(k16 * 32);
            const uint32_t brow = (uint32_t)((k16 * 16) + krow_base) * 512u;
            uint32_t ah[2][4], al[2][4], bb[4][4];
            ldsm4(ah[0], st + a_off[0] + kb2);
            ldsm4(ah[1], st + a_off[1] + kb2);
            ldsm4(al[0], st + OFF_ALO + a_off[0] + kb2);
            ldsm4(al[1], st + OFF_ALO + a_off[1] + kb2);
#pragma unroll
            for (int nt2 = 0; nt2 < 4; nt2++)
                ldsm4t(bb[nt2], st + OFF_B + brow + gg[nt2]);
#pragma unroll
            for (int mt = 0; mt < 2; mt++)
#pragma unroll
                for (int nt = 0; nt < 8; nt++)
                    mma16816h(c[mt][nt], ah[mt], bb[nt >> 1][(nt & 1) * 2],
                              bb[nt >> 1][(nt & 1) * 2 + 1]);
#pragma unroll
            for (int mt = 0; mt < 2; mt++)
#pragma unroll
                for (int nt = 0; nt < 8; nt++)
                    mma16816h(c[mt][nt], al[mt], bb[nt >> 1][(nt & 1) * 2],
                              bb[nt >> 1][(nt & 1) * 2 + 1]);
        }
    };

    // 3-stage pipeline prologue
    issue_loads(0, 0);
    issue_loads(1, 1);
    asm volatile("cp.async.wait_group 1;" ::: "memory");
    __syncthreads();

#pragma unroll 1
    for (int kt = 0; kt < NT2; kt++) {
        const int s = kt % NSTG;
        if (kt + 2 < NT2) issue_loads(kt + 2, (kt + 2) % NSTG);
        compute(s);
        if (kt + 1 < NT2) {
            asm volatile("cp.async.wait_group 1;" ::: "memory");
            __syncthreads();
        }
    }

    if (bx == 8) {
        // root block: Y = c + bias (fp32)
#pragma unroll
        for (int mt = 0; mt < 2; mt++) {
            const int row = m0 + warp_m * 32 + mt * 16 + g;
#pragma unroll
            for (int nt = 0; nt < 8; nt++) {
                const int col = warp_n * 64 + nt * 8 + tc * 2;
                const float b0 = bias[col];
                const float b1 = bias[col + 1];
                *(float2*)&Y[(size_t)row * D_ + col] =
                    make_float2(c[mt][nt][0] + b0, c[mt][nt][1] + b1);
                *(float2*)&Y[(size_t)(row + 8) * D_ + col] =
                    make_float2(c[mt][nt][2] + b0, c[mt][nt][3] + b1);
            }
        }
    } else {
        // relation block: convert to fp16, stage via smem, coalesced store to XW
        __syncthreads();   // all warps done reading stage buffers
#pragma unroll
        for (int mt = 0; mt < 2; mt++) {
#pragma unroll
            for (int h = 0; h < 2; h++) {
                int lrow = warp_m * 32 + mt * 16 + h * 8 + g;
#pragma unroll
                for (int nt = 0; nt < 8; nt++) {
                    int gran = warp_n * 8 + nt;
                    uint32_t off = (uint32_t)lrow * 512 +
                                   ((uint32_t)(gran ^ (lrow & 7)) << 4) + tc * 4;
                    sts4(sbase + off, cvt2h(c[mt][nt][h * 2], c[mt][nt][h * 2 + 1]));
                }
            }
        }
        __syncthreads();
        __half* dst = XW + (size_t)m0 * (R_ * D_) + bx * D_;
#pragma unroll
        for (int p = 0; p < 8; p++) {
            int i = tid + p * 512;          // 4096 16B-chunks
            int row = i >> 5;
            int gran = i & 31;
            uint32_t soff = (uint32_t)row * 512 +
                            ((uint32_t)(gran ^ (row & 7)) << 4);
            uint4 v;
            lds16(v, sbase + soff);
            *(uint4*)(dst + (size_t)row * (R_ * D_) + gran * 8) = v;
        }
    }
}

// ---------------- launch ----------------------------------------------------
extern "C" void kernel_launch(void* const* d_in, const int* in_sizes, int n_in,
                              void* d_out, int out_size) {
    const int*   nodes = (const int*)d_in[0];
    const int*   edges = (const int*)d_in[1];
    const int*   types = (const int*)d_in[2];
    const float* emb   = (const float*)d_in[3];
    const float* W     = (const float*)d_in[4];
    const float* Wroot = (const float*)d_in[5];
    const float* bias  = (const float*)d_in[6];
    float* out = (float*)d_out;

    cudaFuncSetAttribute(rgcn_gemm_mma,
                         cudaFuncAttributeMaxDynamicSharedMemorySize, SMEM_DYN);

    float* y0 = nullptr;
    __half *xw = nullptr, *xhi = nullptr, *xlo = nullptr;
    cudaGetSymbolAddress((void**)&y0, g_y);
    cudaGetSymbolAddress((void**)&xw, g_xw);
    cudaGetSymbolAddress((void**)&xhi, g_xhi);
    cudaGetSymbolAddress((void**)&xlo, g_xlo);

    // CSR build (once; edges are identical for both layers)
    zero_counts<<<M_TOT / 256, 256>>>();
    count_deg<<<(B_ * E_) / 256, 256>>>(edges);
    scan1_kernel<<<128, 256>>>();
    scan2_kernel<<<1, 128>>>();
    scan3_kernel<<<128, 256>>>();
    fill_adj<<<(B_ * E_) / 256, 256>>>(edges, types);

    // layer-0 A: gather + split fused
    asplit0_kernel<<<(M_TOT * 32) / 256, 256>>>(nodes, emb);

    for (int l = 0; l < L_; l++) {
        bconv_kernel<<<(NT2 * NBLK * 1024 + 255) / 256, 256>>>(
            W + (size_t)l * R_ * D_ * D_, Wroot + (size_t)l * D_ * D_);
        float* Yl = (l == L_ - 1) ? out : y0;
        dim3 grid(NBLK, M_TOT / 128);   // (9, 256)
        rgcn_gemm_mma<<<grid, 512, SMEM_DYN>>>(xhi, xlo,
                                               bias + (size_t)l * D_, Yl, xw);
        aggregate_kernel<<<M_TOT / 8, 256>>>(xw, Yl);
        if (l < L_ - 1)
            asplit1_kernel<<<(M_TOT * 32) / 256, 256>>>(Yl);
    }
}

// round 9
// speedup vs baseline: 1.7810x; 1.3695x over previous
#include <cuda_runtime.h>
#include <cuda_fp16.h>
#include <cstdint>
#include <cstddef>

// Problem constants
#define B_   16
#define N_   2048
#define E_   32768
#define D_   256
#define R_   8
#define L_   2

#define M_TOT (B_ * N_)       // 32768 rows
#define KDIM  256             // GEMM K = D
#define KT2   32              // K per stage
#define NT2   (KDIM / KT2)    // 8 stages
#define NBLK  9               // 8 relation col-blocks + 1 root col-block

// ---------------- scratch (device globals; no allocation allowed) ----------
__device__ float g_y[M_TOT * D_];                    // inter-layer output
__device__ __half g_xh[M_TOT * D_];                  // fp16 A
__device__ __half g_xw[(size_t)M_TOT * (R_ * D_)];   // 134 MB fp16 messages
// CSR by destination (built once; edges are layer-invariant)
__device__ int g_degi[M_TOT];
__device__ int g_fill[M_TOT];
__device__ int g_rowptr[M_TOT + 1];
__device__ int g_bsum[128];
__device__ int g_adj[B_ * E_];                       // (r<<15) | src_global
// pre-converted, pre-swizzled fp16 B tiles: [kt(8)*9+bx] x 16384 bytes
__device__ uint8_t g_Bh[NT2 * NBLK * 16384];

// ---------------- smem geometry for the GEMM -------------------------------
#define A_STRIDE  80                       // bytes per 32-fp16 A row (64B + 16 pad)
#define SA_BYTES  (128 * A_STRIDE)         // 10240 for A
#define OFF_B     SA_BYTES                 // 10240 (128B aligned)
#define STAGE     (OFF_B + 16384)          // 26624
#define NSTG      3
#define SMEM_DYN  (NSTG * STAGE + 128)     // 80000

// ---------------- PTX helpers ----------------------------------------------
__device__ __forceinline__ uint32_t smem_u32(const void* p) {
    uint32_t a;
    asm("{ .reg .u64 t; cvta.to.shared.u64 t, %1; cvt.u32.u64 %0, t; }"
        : "=r"(a) : "l"(p));
    return a;
}
__device__ __forceinline__ void ldsm4(uint32_t (&r)[4], uint32_t addr) {
    asm volatile("ldmatrix.sync.aligned.m8n8.x4.shared.b16 {%0,%1,%2,%3}, [%4];"
                 : "=r"(r[0]), "=r"(r[1]), "=r"(r[2]), "=r"(r[3]) : "r"(addr));
}
__device__ __forceinline__ void ldsm4t(uint32_t (&r)[4], uint32_t addr) {
    asm volatile("ldmatrix.sync.aligned.m8n8.x4.trans.shared.b16 {%0,%1,%2,%3}, [%4];"
                 : "=r"(r[0]), "=r"(r[1]), "=r"(r[2]), "=r"(r[3]) : "r"(addr));
}
__device__ __forceinline__ void mma16816h(float (&c)[4], const uint32_t (&a)[4],
                                          uint32_t b0, uint32_t b1) {
    asm volatile("mma.sync.aligned.m16n8k16.row.col.f32.f16.f16.f32 "
                 "{%0,%1,%2,%3}, {%4,%5,%6,%7}, {%8,%9}, {%0,%1,%2,%3};"
                 : "+f"(c[0]), "+f"(c[1]), "+f"(c[2]), "+f"(c[3])
                 : "r"(a[0]), "r"(a[1]), "r"(a[2]), "r"(a[3]), "r"(b0), "r"(b1));
}
__device__ __forceinline__ void cp16(uint32_t dst, const void* src) {
    asm volatile("cp.async.cg.shared.global [%0], [%1], 16;"
                 :: "r"(dst), "l"(src) : "memory");
}
__device__ __forceinline__ void sts4(uint32_t addr, uint32_t v) {
    asm volatile("st.shared.b32 [%0], %1;" :: "r"(addr), "r"(v) : "memory");
}
__device__ __forceinline__ void lds16(uint4& v, uint32_t addr) {
    asm volatile("ld.shared.v4.b32 {%0, %1, %2, %3}, [%4];"
                 : "=r"(v.x), "=r"(v.y), "=r"(v.z), "=r"(v.w) : "r"(addr));
}
__device__ __forceinline__ uint32_t cvt2h(float x0, float x1) {
    __half2 hh = __floats2half2_rn(x0, x1);
    return *(uint32_t*)&hh;
}

// ---------------- A convert kernels -------------------------------------------
// layer 0: gather emb[nodes] and convert to fp16
__global__ void aconv0_kernel(const int* __restrict__ nodes,
                              const float* __restrict__ emb) {
    int idx = blockIdx.x * blockDim.x + threadIdx.x;   // M_TOT*32
    if (idx >= M_TOT * 32) return;
    int node = idx >> 5;
    int q = idx & 31;
    int v = nodes[node];
    const float4* src = (const float4*)(emb + (size_t)v * D_ + q * 8);
    float4 a = src[0];
    float4 b = src[1];
    uint4 h;
    h.x = cvt2h(a.x, a.y);
    h.y = cvt2h(a.z, a.w);
    h.z = cvt2h(b.x, b.y);
    h.w = cvt2h(b.z, b.w);
    *((uint4*)(g_xh) + idx) = h;
}
// between layers: relu(Y) -> fp16
__global__ void aconv1_kernel(const float* __restrict__ Y) {
    int idx = blockIdx.x * blockDim.x + threadIdx.x;
    if (idx >= M_TOT * 32) return;
    const float4* src = (const float4*)Y + idx * 2;
    float4 a = src[0];
    float4 b = src[1];
    uint4 h;
    h.x = cvt2h(fmaxf(a.x, 0.f), fmaxf(a.y, 0.f));
    h.y = cvt2h(fmaxf(a.z, 0.f), fmaxf(a.w, 0.f));
    h.z = cvt2h(fmaxf(b.x, 0.f), fmaxf(b.y, 0.f));
    h.w = cvt2h(fmaxf(b.z, 0.f), fmaxf(b.w, 0.f));
    *((uint4*)(g_xh) + idx) = h;
}

// ---------------- CSR build (once) ------------------------------------------
__global__ void zero_counts() {
    int idx = blockIdx.x * blockDim.x + threadIdx.x;
    if (idx < M_TOT) { g_degi[idx] = 0; g_fill[idx] = 0; }
}
__global__ void count_deg(const int* __restrict__ edges) {
    int idx = blockIdx.x * blockDim.x + threadIdx.x;
    if (idx >= B_ * E_) return;
    int b = idx >> 15;
    int e = idx & (E_ - 1);
    int dst = edges[(size_t)b * 2 * E_ + E_ + e];
    atomicAdd(&g_degi[b * N_ + dst], 1);
}
// phase 1: per-256-block local exclusive scan + block sums (128 CTAs)
__global__ void scan1_kernel() {
    __shared__ int ws[8];
    int b = blockIdx.x, t = threadIdx.x, lane = t & 31, w = t >> 5;
    int i = b * 256 + t;
    int d = g_degi[i];
    int v = d;
#pragma unroll
    for (int off = 1; off < 32; off <<= 1) {
        int u = __shfl_up_sync(0xFFFFFFFFu, v, off);
        if (lane >= off) v += u;
    }
    if (lane == 31) ws[w] = v;
    __syncthreads();
    if (w == 0 && lane < 8) {
        int x = ws[lane];
#pragma unroll
        for (int off = 1; off < 8; off <<= 1) {
            int u = __shfl_up_sync(0xFFu, x, off);
            if (lane >= off) x += u;
        }
        ws[lane] = x;
    }
    __syncthreads();
    int incl = v + (w > 0 ? ws[w - 1] : 0);
    g_rowptr[i] = incl - d;
    if (t == 255) g_bsum[b] = incl;
}
// phase 2: scan the 128 block sums (1 CTA)
__global__ void scan2_kernel() {
    __shared__ int ws[4];
    int t = threadIdx.x, lane = t & 31, w = t >> 5;
    int d = g_bsum[t];
    int v = d;
#pragma unroll
    for (int off = 1; off < 32; off <<= 1) {
        int u = __shfl_up_sync(0xFFFFFFFFu, v, off);
        if (lane >= off) v += u;
    }
    if (lane == 31) ws[w] = v;
    __syncthreads();
    if (w == 0 && lane < 4) {
        int x = ws[lane];
#pragma unroll
        for (int off = 1; off < 4; off <<= 1) {
            int u = __shfl_up_sync(0xFu, x, off);
            if (lane >= off) x += u;
        }
        ws[lane] = x;
    }
    __syncthreads();
    int incl = v + (w > 0 ? ws[w - 1] : 0);
    g_bsum[t] = incl - d;                 // exclusive block offset
    if (t == 127) g_rowptr[M_TOT] = incl; // total (= B_*E_)
}
// phase 3: add block offsets
__global__ void scan3_kernel() {
    int i = blockIdx.x * blockDim.x + threadIdx.x;
    g_rowptr[i] += g_bsum[blockIdx.x];
}
__global__ void fill_adj(const int* __restrict__ edges,
                         const int* __restrict__ types) {
    int idx = blockIdx.x * blockDim.x + threadIdx.x;
    if (idx >= B_ * E_) return;
    int b = idx >> 15;
    int e = idx & (E_ - 1);
    const int* eb = edges + (size_t)b * 2 * E_;
    int src = eb[e];
    int dst = eb[E_ + e];
    int r = types[(size_t)b * E_ + e];
    int gdst = b * N_ + dst;
    int pos = g_rowptr[gdst] + atomicAdd(&g_fill[gdst], 1);
    g_adj[pos] = (r << 15) | (b * N_ + src);
}

// Pre-convert + pre-swizzle W into ldmatrix-ready fp16 tile images.
__global__ void bconv_kernel(const float* __restrict__ Wl,
                             const float* __restrict__ Wr) {
    int gid = blockIdx.x * blockDim.x + threadIdx.x;   // NT2*NBLK*1024
    if (gid >= NT2 * NBLK * 1024) return;
    int tile = gid >> 10;           // kt*9 + bx
    int rem = gid & 1023;
    int krow = rem >> 5;
    int gq = rem & 31;
    int kt = tile / NBLK;
    int bx = tile - kt * NBLK;
    int k = kt * KT2 + krow;
    int n0 = bx * 256 + gq * 8;
    const float* src = (n0 < 2048)
        ? Wl + ((size_t)(n0 >> 8) << 16) + (size_t)k * 256 + (n0 & 255)
        : Wr + (size_t)k * 256 + (n0 - 2048);
    float4 v0 = ((const float4*)src)[0];
    float4 v1 = ((const float4*)src)[1];
    uint4 h;
    h.x = cvt2h(v0.x, v0.y);
    h.y = cvt2h(v0.z, v0.w);
    h.z = cvt2h(v1.x, v1.y);
    h.w = cvt2h(v1.z, v1.w);
    uint32_t off = (uint32_t)tile * 16384u + (uint32_t)krow * 512u +
                   ((uint32_t)(gq ^ (krow & 7)) << 4);
    *(uint4*)(g_Bh + off) = h;
}

// ---------------- atomic-free aggregation ------------------------------------
// One warp per dst node: Y[dst] += (sum over in-edges of xw[src, r, :]) / max(deg,1)
__global__ void __launch_bounds__(256)
aggregate_kernel(const __half* __restrict__ xw, float* __restrict__ Y) {
    int w = (blockIdx.x * blockDim.x + threadIdx.x) >> 5;
    int lane = threadIdx.x & 31;
    if (w >= M_TOT) return;
    int beg = g_rowptr[w];
    int end = g_rowptr[w + 1];

    float acc[8] = {0.f, 0.f, 0.f, 0.f, 0.f, 0.f, 0.f, 0.f};
    int p = beg;
    for (; p + 2 <= end; p += 2) {
        int e0 = g_adj[p];
        int e1 = g_adj[p + 1];
        uint4 v0 = *((const uint4*)(xw + ((size_t)(e0 & 32767) * R_ + (e0 >> 15)) * D_) + lane);
        uint4 v1 = *((const uint4*)(xw + ((size_t)(e1 & 32767) * R_ + (e1 >> 15)) * D_) + lane);
        const __half2* h0 = (const __half2*)&v0;
        const __half2* h1 = (const __half2*)&v1;
#pragma unroll
        for (int j = 0; j < 4; j++) {
            float2 f0 = __half22float2(h0[j]);
            float2 f1 = __half22float2(h1[j]);
            acc[2 * j] += f0.x + f1.x;
            acc[2 * j + 1] += f0.y + f1.y;
        }
    }
    if (p < end) {
        int e0 = g_adj[p];
        uint4 v0 = *((const uint4*)(xw + ((size_t)(e0 & 32767) * R_ + (e0 >> 15)) * D_) + lane);
        const __half2* h0 = (const __half2*)&v0;
#pragma unroll
        for (int j = 0; j < 4; j++) {
            float2 f0 = __half22float2(h0[j]);
            acc[2 * j] += f0.x;
            acc[2 * j + 1] += f0.y;
        }
    }
    float idg = 1.0f / (float)((end - beg) > 1 ? (end - beg) : 1);
    float* yp = Y + (size_t)w * D_ + lane * 8;
    float4 y0 = *(float4*)yp;
    float4 y1 = *(float4*)(yp + 4);
    y0.x += acc[0] * idg; y0.y += acc[1] * idg;
    y0.z += acc[2] * idg; y0.w += acc[3] * idg;
    y1.x += acc[4] * idg; y1.y += acc[5] * idg;
    y1.z += acc[6] * idg; y1.w += acc[7] * idg;
    *(float4*)yp = y0;
    *(float4*)(yp + 4) = y1;
}

// ---------------- warp-MMA GEMM ----------------------------------------------
// CTA: 128 rows x 256 cols of xw = Xh @ [W_cat | W_root] (single-pass fp16).
// grid (9, 256): bx<8 -> fp16 to g_xw (smem-staged); bx==8 -> Y = . + bias
__global__ void __launch_bounds__(512, 1)
rgcn_gemm_mma(const __half* __restrict__ Xh,
              const float* __restrict__ bias,
              float* __restrict__ Y,
              __half* __restrict__ XW) {
    extern __shared__ uint8_t smem_raw[];
    const uint32_t sbase = (smem_u32(smem_raw) + 127u) & ~127u;

    const int tid = threadIdx.x;
    const int lane = tid & 31;
    const int wid = tid >> 5;
    const int warp_m = wid & 3;      // 4 warps along M (32 rows each)
    const int warp_n = wid >> 2;     // 4 warps along N (64 cols each)
    const int bx = blockIdx.x;
    const int m0 = blockIdx.y * 128;

    // A fill mapping: 4 threads per row, one 16B chunk (8 halves) each
    const int arow = tid >> 2;
    const int ac = tid & 3;
    const uint32_t a_sts = (uint32_t)arow * A_STRIDE + (uint32_t)ac * 16;
    const size_t a_goff = (size_t)(m0 + arow) * KDIM + ac * 8;

    const int g = lane >> 2;
    const int tc = lane & 3;

    // ldmatrix address pieces
    uint32_t a_off[2];
#pragma unroll
    for (int mt = 0; mt < 2; mt++)
        a_off[mt] = (uint32_t)(warp_m * 32 + mt * 16 + (lane & 15)) * A_STRIDE +
                    (uint32_t)((lane >> 4) * 16);
    const uint32_t krow_base = (uint32_t)((lane & 7) + ((lane >> 3) & 1) * 8);
    uint32_t gg[4];
#pragma unroll
    for (int nt2 = 0; nt2 < 4; nt2++)
        gg[nt2] = (uint32_t)(((warp_n * 8 + nt2 * 2 + (lane >> 4)) ^ (lane & 7)) << 4);

    float c[2][8][4];
#pragma unroll
    for (int mt = 0; mt < 2; mt++)
#pragma unroll
        for (int nt = 0; nt < 8; nt++)
#pragma unroll
            for (int j = 0; j < 4; j++) c[mt][nt][j] = 0.f;

    auto issue_loads = [&](int kt, int s) {
        const uint32_t st = sbase + (uint32_t)s * STAGE;
        const uint8_t* bh = g_Bh + (size_t)(kt * NBLK + bx) * 16384 + tid * 16;
        cp16(st + OFF_B + tid * 16, bh);
        cp16(st + OFF_B + 8192 + tid * 16, bh + 8192);
        cp16(st + a_sts, Xh + a_goff + kt * KT2);
        asm volatile("cp.async.commit_group;" ::: "memory");
    };

    auto compute = [&](int s) {
        const uint32_t st = sbase + (uint32_t)s * STAGE;
#pragma unroll
        for (int k16 = 0; k16 < 2; k16++) {
            const uint32_t kb2 = (uint32_t)(k16 * 32);
            const uint32_t brow = (uint32_t)((k16 * 16) + krow_base) * 512u;
            uint32_t ah[2][4], bb[4][4];
            ldsm4(ah[0], st + a_off[0] + kb2);
            ldsm4(ah[1], st + a_off[1] + kb2);
#pragma unroll
            for (int nt2 = 0; nt2 < 4; nt2++)
                ldsm4t(bb[nt2], st + OFF_B + brow + gg[nt2]);
#pragma unroll
            for (int mt = 0; mt < 2; mt++)
#pragma unroll
                for (int nt = 0; nt < 8; nt++)
                    mma16816h(c[mt][nt], ah[mt], bb[nt >> 1][(nt & 1) * 2],
                              bb[nt >> 1][(nt & 1) * 2 + 1]);
        }
    };

    // 3-stage pipeline prologue
    issue_loads(0, 0);
    issue_loads(1, 1);
    asm volatile("cp.async.wait_group 1;" ::: "memory");
    __syncthreads();

#pragma unroll 1
    for (int kt = 0; kt < NT2; kt++) {
        const int s = kt % NSTG;
        if (kt + 2 < NT2) issue_loads(kt + 2, (kt + 2) % NSTG);
        compute(s);
        if (kt + 1 < NT2) {
            asm volatile("cp.async.wait_group 1;" ::: "memory");
            __syncthreads();
        }
    }

    if (bx == 8) {
        // root block: Y = c + bias (fp32)
#pragma unroll
        for (int mt = 0; mt < 2; mt++) {
            const int row = m0 + warp_m * 32 + mt * 16 + g;
#pragma unroll
            for (int nt = 0; nt < 8; nt++) {
                const int col = warp_n * 64 + nt * 8 + tc * 2;
                const float b0 = bias[col];
                const float b1 = bias[col + 1];
                *(float2*)&Y[(size_t)row * D_ + col] =
                    make_float2(c[mt][nt][0] + b0, c[mt][nt][1] + b1);
                *(float2*)&Y[(size_t)(row + 8) * D_ + col] =
                    make_float2(c[mt][nt][2] + b0, c[mt][nt][3] + b1);
            }
        }
    } else {
        // relation block: convert to fp16, stage via smem, coalesced store to XW
        __syncthreads();   // all warps done reading stage buffers
#pragma unroll
        for (int mt = 0; mt < 2; mt++) {
#pragma unroll
            for (int h = 0; h < 2; h++) {
                int lrow = warp_m * 32 + mt * 16 + h * 8 + g;
#pragma unroll
                for (int nt = 0; nt < 8; nt++) {
                    int gran = warp_n * 8 + nt;
                    uint32_t off = (uint32_t)lrow * 512 +
                                   ((uint32_t)(gran ^ (lrow & 7)) << 4) + tc * 4;
                    sts4(sbase + off, cvt2h(c[mt][nt][h * 2], c[mt][nt][h * 2 + 1]));
                }
            }
        }
        __syncthreads();
        __half* dst = XW + (size_t)m0 * (R_ * D_) + bx * D_;
#pragma unroll
        for (int p = 0; p < 8; p++) {
            int i = tid + p * 512;          // 4096 16B-chunks
            int row = i >> 5;
            int gran = i & 31;
            uint32_t soff = (uint32_t)row * 512 +
                            ((uint32_t)(gran ^ (row & 7)) << 4);
            uint4 v;
            lds16(v, sbase + soff);
            *(uint4*)(dst + (size_t)row * (R_ * D_) + gran * 8) = v;
        }
    }
}

// ---------------- launch ----------------------------------------------------
extern "C" void kernel_launch(void* const* d_in, const int* in_sizes, int n_in,
                              void* d_out, int out_size) {
    const int*   nodes = (const int*)d_in[0];
    const int*   edges = (const int*)d_in[1];
    const int*   types = (const int*)d_in[2];
    const float* emb   = (const float*)d_in[3];
    const float* W     = (const float*)d_in[4];
    const float* Wroot = (const float*)d_in[5];
    const float* bias  = (const float*)d_in[6];
    float* out = (float*)d_out;

    cudaFuncSetAttribute(rgcn_gemm_mma,
                         cudaFuncAttributeMaxDynamicSharedMemorySize, SMEM_DYN);

    float* y0 = nullptr;
    __half *xw = nullptr, *xh = nullptr;
    cudaGetSymbolAddress((void**)&y0, g_y);
    cudaGetSymbolAddress((void**)&xw, g_xw);
    cudaGetSymbolAddress((void**)&xh, g_xh);

    // CSR build (once; edges are identical for both layers)
    zero_counts<<<M_TOT / 256, 256>>>();
    count_deg<<<(B_ * E_) / 256, 256>>>(edges);
    scan1_kernel<<<128, 256>>>();
    scan2_kernel<<<1, 128>>>();
    scan3_kernel<<<128, 256>>>();
    fill_adj<<<(B_ * E_) / 256, 256>>>(edges, types);

    // layer-0 A: gather + convert fused
    aconv0_kernel<<<(M_TOT * 32) / 256, 256>>>(nodes, emb);

    for (int l = 0; l < L_; l++) {
        bconv_kernel<<<(NT2 * NBLK * 1024 + 255) / 256, 256>>>(
            W + (size_t)l * R_ * D_ * D_, Wroot + (size_t)l * D_ * D_);
        float* Yl = (l == L_ - 1) ? out : y0;
        dim3 grid(NBLK, M_TOT / 128);   // (9, 256)
        rgcn_gemm_mma<<<grid, 512, SMEM_DYN>>>(xh, bias + (size_t)l * D_, Yl, xw);
        aggregate_kernel<<<M_TOT / 8, 256>>>(xw, Yl);
        if (l < L_ - 1)
            aconv1_kernel<<<(M_TOT * 32) / 256, 256>>>(Yl);
    }
}

// round 10
// speedup vs baseline: 2.0108x; 1.1290x over previous
#include <cuda_runtime.h>
#include <cuda_fp16.h>
#include <cstdint>
#include <cstddef>

// Problem constants
#define B_   16
#define N_   2048
#define E_   32768
#define D_   256
#define R_   8
#define L_   2

#define M_TOT (B_ * N_)       // 32768 rows
#define KDIM  256             // GEMM K = D
#define KT2   32              // K per stage
#define NT2   (KDIM / KT2)    // 8 stages
#define NBLK  18              // 16 relation col-blocks + 2 root col-blocks (128 each)

// ---------------- scratch (device globals; no allocation allowed) ----------
__device__ float g_y[M_TOT * D_];                    // layer-0 root output
__device__ __half g_xh[M_TOT * D_];                  // fp16 A
__device__ __half g_xw[(size_t)M_TOT * (R_ * D_)];   // 134 MB fp16 messages
// CSR by destination (built once; edges are layer-invariant)
__device__ int g_degi[M_TOT];
__device__ int g_fill[M_TOT];
__device__ int g_rowptr[M_TOT + 1];
__device__ int g_bsum[128];
__device__ int g_adj[B_ * E_];                       // (r<<15) | src_global
// pre-converted, pre-swizzled fp16 B tiles: [l(2)][kt(8)][bx(18)] x 8192 bytes
__device__ uint8_t g_Bh[L_ * NT2 * NBLK * 8192];

// ---------------- smem geometry for the GEMM -------------------------------
#define A_STRIDE  80                       // bytes per 32-fp16 A row (64B + 16 pad)
#define SA_BYTES  (128 * A_STRIDE)         // 10240 for A
#define OFF_B     SA_BYTES                 // 10240 (128B aligned? 10240 = 80*128 ok mod 16)
#define STAGE     (OFF_B + 8192)           // 18432
#define NSTG      3
#define SMEM_DYN  (NSTG * STAGE + 128)     // 55424

// ---------------- PTX helpers ----------------------------------------------
__device__ __forceinline__ uint32_t smem_u32(const void* p) {
    uint32_t a;
    asm("{ .reg .u64 t; cvta.to.shared.u64 t, %1; cvt.u32.u64 %0, t; }"
        : "=r"(a) : "l"(p));
    return a;
}
__device__ __forceinline__ void ldsm4(uint32_t (&r)[4], uint32_t addr) {
    asm volatile("ldmatrix.sync.aligned.m8n8.x4.shared.b16 {%0,%1,%2,%3}, [%4];"
                 : "=r"(r[0]), "=r"(r[1]), "=r"(r[2]), "=r"(r[3]) : "r"(addr));
}
__device__ __forceinline__ void ldsm4t(uint32_t (&r)[4], uint32_t addr) {
    asm volatile("ldmatrix.sync.aligned.m8n8.x4.trans.shared.b16 {%0,%1,%2,%3}, [%4];"
                 : "=r"(r[0]), "=r"(r[1]), "=r"(r[2]), "=r"(r[3]) : "r"(addr));
}
__device__ __forceinline__ void mma16816h(float (&c)[4], const uint32_t (&a)[4],
                                          uint32_t b0, uint32_t b1) {
    asm volatile("mma.sync.aligned.m16n8k16.row.col.f32.f16.f16.f32 "
                 "{%0,%1,%2,%3}, {%4,%5,%6,%7}, {%8,%9}, {%0,%1,%2,%3};"
                 : "+f"(c[0]), "+f"(c[1]), "+f"(c[2]), "+f"(c[3])
                 : "r"(a[0]), "r"(a[1]), "r"(a[2]), "r"(a[3]), "r"(b0), "r"(b1));
}
__device__ __forceinline__ void cp16(uint32_t dst, const void* src) {
    asm volatile("cp.async.cg.shared.global [%0], [%1], 16;"
                 :: "r"(dst), "l"(src) : "memory");
}
__device__ __forceinline__ void sts4(uint32_t addr, uint32_t v) {
    asm volatile("st.shared.b32 [%0], %1;" :: "r"(addr), "r"(v) : "memory");
}
__device__ __forceinline__ void lds16(uint4& v, uint32_t addr) {
    asm volatile("ld.shared.v4.b32 {%0, %1, %2, %3}, [%4];"
                 : "=r"(v.x), "=r"(v.y), "=r"(v.z), "=r"(v.w) : "r"(addr));
}
__device__ __forceinline__ uint32_t cvt2h(float x0, float x1) {
    __half2 hh = __floats2half2_rn(x0, x1);
    return *(uint32_t*)&hh;
}

// ---------------- A convert (layer 0: gather + convert) ----------------------
__global__ void aconv0_kernel(const int* __restrict__ nodes,
                              const float* __restrict__ emb) {
    int idx = blockIdx.x * blockDim.x + threadIdx.x;   // M_TOT*32
    if (idx >= M_TOT * 32) return;
    int node = idx >> 5;
    int q = idx & 31;
    int v = nodes[node];
    const float4* src = (const float4*)(emb + (size_t)v * D_ + q * 8);
    float4 a = src[0];
    float4 b = src[1];
    uint4 h;
    h.x = cvt2h(a.x, a.y);
    h.y = cvt2h(a.z, a.w);
    h.z = cvt2h(b.x, b.y);
    h.w = cvt2h(b.z, b.w);
    *((uint4*)(g_xh) + idx) = h;
}

// ---------------- CSR build (once) ------------------------------------------
__global__ void zero_counts() {
    int idx = blockIdx.x * blockDim.x + threadIdx.x;
    if (idx < M_TOT) { g_degi[idx] = 0; g_fill[idx] = 0; }
}
__global__ void count_deg(const int* __restrict__ edges) {
    int idx = blockIdx.x * blockDim.x + threadIdx.x;
    if (idx >= B_ * E_) return;
    int b = idx >> 15;
    int e = idx & (E_ - 1);
    int dst = edges[(size_t)b * 2 * E_ + E_ + e];
    atomicAdd(&g_degi[b * N_ + dst], 1);
}
__global__ void scan1_kernel() {
    __shared__ int ws[8];
    int b = blockIdx.x, t = threadIdx.x, lane = t & 31, w = t >> 5;
    int i = b * 256 + t;
    int d = g_degi[i];
    int v = d;
#pragma unroll
    for (int off = 1; off < 32; off <<= 1) {
        int u = __shfl_up_sync(0xFFFFFFFFu, v, off);
        if (lane >= off) v += u;
    }
    if (lane == 31) ws[w] = v;
    __syncthreads();
    if (w == 0 && lane < 8) {
        int x = ws[lane];
#pragma unroll
        for (int off = 1; off < 8; off <<= 1) {
            int u = __shfl_up_sync(0xFFu, x, off);
            if (lane >= off) x += u;
        }
        ws[lane] = x;
    }
    __syncthreads();
    int incl = v + (w > 0 ? ws[w - 1] : 0);
    g_rowptr[i] = incl - d;
    if (t == 255) g_bsum[b] = incl;
}
__global__ void scan2_kernel() {
    __shared__ int ws[4];
    int t = threadIdx.x, lane = t & 31, w = t >> 5;
    int d = g_bsum[t];
    int v = d;
#pragma unroll
    for (int off = 1; off < 32; off <<= 1) {
        int u = __shfl_up_sync(0xFFFFFFFFu, v, off);
        if (lane >= off) v += u;
    }
    if (lane == 31) ws[w] = v;
    __syncthreads();
    if (w == 0 && lane < 4) {
        int x = ws[lane];
#pragma unroll
        for (int off = 1; off < 4; off <<= 1) {
            int u = __shfl_up_sync(0xFu, x, off);
            if (lane >= off) x += u;
        }
        ws[lane] = x;
    }
    __syncthreads();
    int incl = v + (w > 0 ? ws[w - 1] : 0);
    g_bsum[t] = incl - d;
    if (t == 127) g_rowptr[M_TOT] = incl;
}
__global__ void scan3_kernel() {
    int i = blockIdx.x * blockDim.x + threadIdx.x;
    g_rowptr[i] += g_bsum[blockIdx.x];
}
__global__ void fill_adj(const int* __restrict__ edges,
                         const int* __restrict__ types) {
    int idx = blockIdx.x * blockDim.x + threadIdx.x;
    if (idx >= B_ * E_) return;
    int b = idx >> 15;
    int e = idx & (E_ - 1);
    const int* eb = edges + (size_t)b * 2 * E_;
    int src = eb[e];
    int dst = eb[E_ + e];
    int r = types[(size_t)b * E_ + e];
    int gdst = b * N_ + dst;
    int pos = g_rowptr[gdst] + atomicAdd(&g_fill[gdst], 1);
    g_adj[pos] = (r << 15) | (b * N_ + src);
}

// Pre-convert + pre-swizzle W (BOTH layers) into ldmatrix-ready fp16 tiles.
// Logical B[k][n] = (n < 2048) ? W[l][n>>8][k][n&255] : Wroot[l][k][n-2048]
// Tile (l,kt,bx) image: [krow 0..31][granule g 0..15], row stride 256B,
//   byte_off = krow*256 + ((g ^ (krow & 7)) * 16); g covers n = bx*128 + g*8..+7
__global__ void bconv_kernel(const float* __restrict__ W,
                             const float* __restrict__ Wroot) {
    int gid = blockIdx.x * blockDim.x + threadIdx.x;   // 2*8*18*512 = 147456
    if (gid >= L_ * NT2 * NBLK * 512) return;
    int tile = gid >> 9;
    int rem = gid & 511;
    int krow = rem >> 4;
    int gq = rem & 15;
    int l = tile / (NT2 * NBLK);
    int t2 = tile - l * (NT2 * NBLK);
    int kt = t2 / NBLK;
    int bx = t2 - kt * NBLK;
    int k = kt * KT2 + krow;
    int n0 = bx * 128 + gq * 8;
    const float* src = (n0 < 2048)
        ? W + (size_t)l * R_ * D_ * D_ + ((size_t)(n0 >> 8) << 16) + (size_t)k * 256 + (n0 & 255)
        : Wroot + (size_t)l * D_ * D_ + (size_t)k * 256 + (n0 - 2048);
    float4 v0 = ((const float4*)src)[0];
    float4 v1 = ((const float4*)src)[1];
    uint4 h;
    h.x = cvt2h(v0.x, v0.y);
    h.y = cvt2h(v0.z, v0.w);
    h.z = cvt2h(v1.x, v1.y);
    h.w = cvt2h(v1.z, v1.w);
    uint32_t off = (uint32_t)tile * 8192u + (uint32_t)krow * 256u +
                   ((uint32_t)(gq ^ (krow & 7)) << 4);
    *(uint4*)(g_Bh + off) = h;
}

// ---------------- atomic-free aggregation (fused epilogue) -------------------
// One warp per dst node. mode:
//   xh_out != 0: g_xh[dst] = fp16(relu(Yin[dst] + agg/deg))   (layer 0)
//   xh_out == 0: Yin[dst] += agg/deg                          (final layer)
__global__ void __launch_bounds__(256)
aggregate_kernel(const __half* __restrict__ xw, float* __restrict__ Yin,
                 __half* __restrict__ xh_out) {
    int w = (blockIdx.x * blockDim.x + threadIdx.x) >> 5;
    int lane = threadIdx.x & 31;
    if (w >= M_TOT) return;
    int beg = g_rowptr[w];
    int end = g_rowptr[w + 1];

    float acc[8] = {0.f, 0.f, 0.f, 0.f, 0.f, 0.f, 0.f, 0.f};
    int p = beg;
    for (; p + 2 <= end; p += 2) {
        int e0 = g_adj[p];
        int e1 = g_adj[p + 1];
        uint4 v0 = *((const uint4*)(xw + ((size_t)(e0 & 32767) * R_ + (e0 >> 15)) * D_) + lane);
        uint4 v1 = *((const uint4*)(xw + ((size_t)(e1 & 32767) * R_ + (e1 >> 15)) * D_) + lane);
        const __half2* h0 = (const __half2*)&v0;
        const __half2* h1 = (const __half2*)&v1;
#pragma unroll
        for (int j = 0; j < 4; j++) {
            float2 f0 = __half22float2(h0[j]);
            float2 f1 = __half22float2(h1[j]);
            acc[2 * j] += f0.x + f1.x;
            acc[2 * j + 1] += f0.y + f1.y;
        }
    }
    if (p < end) {
        int e0 = g_adj[p];
        uint4 v0 = *((const uint4*)(xw + ((size_t)(e0 & 32767) * R_ + (e0 >> 15)) * D_) + lane);
        const __half2* h0 = (const __half2*)&v0;
#pragma unroll
        for (int j = 0; j < 4; j++) {
            float2 f0 = __half22float2(h0[j]);
            acc[2 * j] += f0.x;
            acc[2 * j + 1] += f0.y;
        }
    }
    float idg = 1.0f / (float)((end - beg) > 1 ? (end - beg) : 1);
    float* yp = Yin + (size_t)w * D_ + lane * 8;
    float4 y0 = *(float4*)yp;
    float4 y1 = *(float4*)(yp + 4);
    y0.x += acc[0] * idg; y0.y += acc[1] * idg;
    y0.z += acc[2] * idg; y0.w += acc[3] * idg;
    y1.x += acc[4] * idg; y1.y += acc[5] * idg;
    y1.z += acc[6] * idg; y1.w += acc[7] * idg;
    if (xh_out) {
        uint4 h;
        h.x = cvt2h(fmaxf(y0.x, 0.f), fmaxf(y0.y, 0.f));
        h.y = cvt2h(fmaxf(y0.z, 0.f), fmaxf(y0.w, 0.f));
        h.z = cvt2h(fmaxf(y1.x, 0.f), fmaxf(y1.y, 0.f));
        h.w = cvt2h(fmaxf(y1.z, 0.f), fmaxf(y1.w, 0.f));
        *((uint4*)(xh_out + (size_t)w * D_) + lane) = h;
    } else {
        *(float4*)yp = y0;
        *(float4*)(yp + 4) = y1;
    }
}

// ---------------- warp-MMA GEMM ----------------------------------------------
// CTA: 128 rows x 128 cols, 256 threads (8 warps: 4M x 2N), 2 CTAs/SM.
// grid (18, 256): bx<16 -> fp16 to XW (smem-staged); bx>=16 -> Y = . + bias
__global__ void __launch_bounds__(256, 2)
rgcn_gemm_mma(const __half* __restrict__ Xh,
              const uint8_t* __restrict__ Bt,
              const float* __restrict__ bias,
              float* __restrict__ Y,
              __half* __restrict__ XW) {
    extern __shared__ uint8_t smem_raw[];
    const uint32_t sbase = (smem_u32(smem_raw) + 127u) & ~127u;

    const int tid = threadIdx.x;
    const int lane = tid & 31;
    const int wid = tid >> 5;
    const int warp_m = wid & 3;      // 4 warps along M (32 rows each)
    const int warp_n = wid >> 2;     // 2 warps along N (64 cols each)
    const int bx = blockIdx.x;
    const int m0 = blockIdx.y * 128;

    // A fill mapping: 2 threads per row, 16 halves (2 cp16) each
    const int arow = tid >> 1;
    const int ac = tid & 1;
    const uint32_t a_sts = (uint32_t)arow * A_STRIDE + (uint32_t)ac * 32;
    const size_t a_goff = (size_t)(m0 + arow) * KDIM + ac * 16;

    const int g = lane >> 2;
    const int tc = lane & 3;

    // ldmatrix address pieces
    uint32_t a_off[2];
#pragma unroll
    for (int mt = 0; mt < 2; mt++)
        a_off[mt] = (uint32_t)(warp_m * 32 + mt * 16 + (lane & 15)) * A_STRIDE +
                    (uint32_t)((lane >> 4) * 16);
    const uint32_t krow_base = (uint32_t)((lane & 7) + ((lane >> 3) & 1) * 8);
    uint32_t gg[4];
#pragma unroll
    for (int nt2 = 0; nt2 < 4; nt2++)
        gg[nt2] = (uint32_t)(((warp_n * 8 + nt2 * 2 + (lane >> 4)) ^ (lane & 7)) << 4);

    float c[2][8][4];
#pragma unroll
    for (int mt = 0; mt < 2; mt++)
#pragma unroll
        for (int nt = 0; nt < 8; nt++)
#pragma unroll
            for (int j = 0; j < 4; j++) c[mt][nt][j] = 0.f;

    auto issue_loads = [&](int kt, int s) {
        const uint32_t st = sbase + (uint32_t)s * STAGE;
        const uint8_t* bh = Bt + (size_t)(kt * NBLK + bx) * 8192 + tid * 16;
        cp16(st + OFF_B + tid * 16, bh);
        cp16(st + OFF_B + 4096 + tid * 16, bh + 4096);
        cp16(st + a_sts, Xh + a_goff + kt * KT2);
        cp16(st + a_sts + 16, Xh + a_goff + kt * KT2 + 8);
        asm volatile("cp.async.commit_group;" ::: "memory");
    };

    auto compute = [&](int s) {
        const uint32_t st = sbase + (uint32_t)s * STAGE;
#pragma unroll
        for (int k16 = 0; k16 < 2; k16++) {
            const uint32_t kb2 = (uint32_t)(k16 * 32);
            const uint32_t brow = (uint32_t)((k16 * 16) + krow_base) * 256u;
            uint32_t ah[2][4], bb[4][4];
            ldsm4(ah[0], st + a_off[0] + kb2);
            ldsm4(ah[1], st + a_off[1] + kb2);
#pragma unroll
            for (int nt2 = 0; nt2 < 4; nt2++)
                ldsm4t(bb[nt2], st + OFF_B + brow + gg[nt2]);
#pragma unroll
            for (int mt = 0; mt < 2; mt++)
#pragma unroll
                for (int nt = 0; nt < 8; nt++)
                    mma16816h(c[mt][nt], ah[mt], bb[nt >> 1][(nt & 1) * 2],
                              bb[nt >> 1][(nt & 1) * 2 + 1]);
        }
    };

    // 3-stage pipeline prologue
    issue_loads(0, 0);
    issue_loads(1, 1);
    asm volatile("cp.async.wait_group 1;" ::: "memory");
    __syncthreads();

#pragma unroll 1
    for (int kt = 0; kt < NT2; kt++) {
        const int s = kt % NSTG;
        if (kt + 2 < NT2) issue_loads(kt + 2, (kt + 2) % NSTG);
        compute(s);
        if (kt + 1 < NT2) {
            asm volatile("cp.async.wait_group 1;" ::: "memory");
            __syncthreads();
        }
    }

    if (bx >= 16) {
        // root block: Y = c + bias (fp32)
        const int col0 = (bx - 16) * 128;
#pragma unroll
        for (int mt = 0; mt < 2; mt++) {
            const int row = m0 + warp_m * 32 + mt * 16 + g;
#pragma unroll
            for (int nt = 0; nt < 8; nt++) {
                const int col = col0 + warp_n * 64 + nt * 8 + tc * 2;
                const float b0 = bias[col];
                const float b1 = bias[col + 1];
                *(float2*)&Y[(size_t)row * D_ + col] =
                    make_float2(c[mt][nt][0] + b0, c[mt][nt][1] + b1);
                *(float2*)&Y[(size_t)(row + 8) * D_ + col] =
                    make_float2(c[mt][nt][2] + b0, c[mt][nt][3] + b1);
            }
        }
    } else {
        // relation block: convert to fp16, stage via smem, coalesced store to XW
        __syncthreads();   // all warps done reading stage buffers
#pragma unroll
        for (int mt = 0; mt < 2; mt++) {
#pragma unroll
            for (int h = 0; h < 2; h++) {
                int lrow = warp_m * 32 + mt * 16 + h * 8 + g;
#pragma unroll
                for (int nt = 0; nt < 8; nt++) {
                    int gran = warp_n * 8 + nt;
                    uint32_t off = (uint32_t)lrow * 256 +
                                   ((uint32_t)(gran ^ (lrow & 7)) << 4) + tc * 4;
                    sts4(sbase + off, cvt2h(c[mt][nt][h * 2], c[mt][nt][h * 2 + 1]));
                }
            }
        }
        __syncthreads();
        __half* dst = XW + (size_t)m0 * (R_ * D_) + bx * 128;
#pragma unroll
        for (int p = 0; p < 8; p++) {
            int i = tid + p * 256;          // 2048 16B-chunks
            int row = i >> 4;
            int gran = i & 15;
            uint32_t soff = (uint32_t)row * 256 +
                            ((uint32_t)(gran ^ (row & 7)) << 4);
            uint4 v;
            lds16(v, sbase + soff);
            *(uint4*)(dst + (size_t)row * (R_ * D_) + gran * 8) = v;
        }
    }
}

// ---------------- launch ----------------------------------------------------
extern "C" void kernel_launch(void* const* d_in, const int* in_sizes, int n_in,
                              void* d_out, int out_size) {
    const int*   nodes = (const int*)d_in[0];
    const int*   edges = (const int*)d_in[1];
    const int*   types = (const int*)d_in[2];
    const float* emb   = (const float*)d_in[3];
    const float* W     = (const float*)d_in[4];
    const float* Wroot = (const float*)d_in[5];
    const float* bias  = (const float*)d_in[6];
    float* out = (float*)d_out;

    cudaFuncSetAttribute(rgcn_gemm_mma,
                         cudaFuncAttributeMaxDynamicSharedMemorySize, SMEM_DYN);

    float* y0 = nullptr;
    __half *xw = nullptr, *xh = nullptr;
    uint8_t* bh = nullptr;
    cudaGetSymbolAddress((void**)&y0, g_y);
    cudaGetSymbolAddress((void**)&xw, g_xw);
    cudaGetSymbolAddress((void**)&xh, g_xh);
    cudaGetSymbolAddress((void**)&bh, g_Bh);

    // weight tiles for BOTH layers, up front (one launch)
    bconv_kernel<<<(L_ * NT2 * NBLK * 512) / 256, 256>>>(W, Wroot);
    // layer-0 A: gather + convert fused
    aconv0_kernel<<<(M_TOT * 32) / 256, 256>>>(nodes, emb);

    // CSR build (once; edges are identical for both layers)
    zero_counts<<<M_TOT / 256, 256>>>();
    count_deg<<<(B_ * E_) / 256, 256>>>(edges);
    scan1_kernel<<<128, 256>>>();
    scan2_kernel<<<1, 128>>>();
    scan3_kernel<<<128, 256>>>();
    fill_adj<<<(B_ * E_) / 256, 256>>>(edges, types);

    dim3 grid(NBLK, M_TOT / 128);   // (18, 256)
    // layer 0
    rgcn_gemm_mma<<<grid, 256, SMEM_DYN>>>(xh, bh, bias, y0, xw);
    aggregate_kernel<<<M_TOT / 8, 256>>>(xw, y0, xh);   // fused relu+fp16 convert
    // layer 1 (final)
    rgcn_gemm_mma<<<grid, 256, SMEM_DYN>>>(xh, bh + (size_t)NT2 * NBLK * 8192,
                                           bias + D_, out, xw);
    aggregate_kernel<<<M_TOT / 8, 256>>>(xw, out, nullptr);
}

// round 11
// speedup vs baseline: 2.0760x; 1.0324x over previous
#include <cuda_runtime.h>
#include <cuda_fp16.h>
#include <cstdint>
#include <cstddef>

// Problem constants
#define B_   16
#define N_   2048
#define E_   32768
#define D_   256
#define R_   8
#define L_   2

#define M_TOT (B_ * N_)       // 32768 rows
#define KDIM  256             // GEMM K = D
#define KT2   32              // K per stage
#define NT2   (KDIM / KT2)    // 8 stages
#define NBLK  18              // 16 relation col-blocks + 2 root col-blocks (128 each)

// ---------------- scratch (device globals; no allocation allowed) ----------
__device__ float g_y[M_TOT * D_];                    // layer-0 root output
__device__ __half g_xh[M_TOT * D_];                  // fp16 A
__device__ __half g_xw[(size_t)M_TOT * (R_ * D_)];   // 134 MB fp16 messages
// CSR by destination (built once; edges are layer-invariant)
__device__ int g_degi[M_TOT];
__device__ int g_fill[M_TOT];
__device__ int g_rowptr[M_TOT + 1];
__device__ int g_bsum[128];
__device__ int g_adj[B_ * E_];                       // (r<<15) | src_global
// pre-converted, pre-swizzled fp16 B tiles: [l(2)][kt(8)][bx(18)] x 8192 bytes
__device__ uint8_t g_Bh[L_ * NT2 * NBLK * 8192];

// ---------------- smem geometry for the GEMM -------------------------------
#define A_STRIDE  80                       // bytes per 32-fp16 A row (64B + 16 pad)
#define SA_BYTES  (128 * A_STRIDE)         // 10240 for A
#define OFF_B     SA_BYTES                 // 10240
#define STAGE     (OFF_B + 8192)           // 18432
#define NSTG      3
#define SMEM_DYN  (NSTG * STAGE + 128)     // 55424

// ---------------- PTX helpers ----------------------------------------------
__device__ __forceinline__ uint32_t smem_u32(const void* p) {
    uint32_t a;
    asm("{ .reg .u64 t; cvta.to.shared.u64 t, %1; cvt.u32.u64 %0, t; }"
        : "=r"(a) : "l"(p));
    return a;
}
__device__ __forceinline__ void ldsm4(uint32_t (&r)[4], uint32_t addr) {
    asm volatile("ldmatrix.sync.aligned.m8n8.x4.shared.b16 {%0,%1,%2,%3}, [%4];"
                 : "=r"(r[0]), "=r"(r[1]), "=r"(r[2]), "=r"(r[3]) : "r"(addr));
}
__device__ __forceinline__ void ldsm4t(uint32_t (&r)[4], uint32_t addr) {
    asm volatile("ldmatrix.sync.aligned.m8n8.x4.trans.shared.b16 {%0,%1,%2,%3}, [%4];"
                 : "=r"(r[0]), "=r"(r[1]), "=r"(r[2]), "=r"(r[3]) : "r"(addr));
}
__device__ __forceinline__ void mma16816h(float (&c)[4], const uint32_t (&a)[4],
                                          uint32_t b0, uint32_t b1) {
    asm volatile("mma.sync.aligned.m16n8k16.row.col.f32.f16.f16.f32 "
                 "{%0,%1,%2,%3}, {%4,%5,%6,%7}, {%8,%9}, {%0,%1,%2,%3};"
                 : "+f"(c[0]), "+f"(c[1]), "+f"(c[2]), "+f"(c[3])
                 : "r"(a[0]), "r"(a[1]), "r"(a[2]), "r"(a[3]), "r"(b0), "r"(b1));
}
__device__ __forceinline__ void cp16(uint32_t dst, const void* src) {
    asm volatile("cp.async.cg.shared.global [%0], [%1], 16;"
                 :: "r"(dst), "l"(src) : "memory");
}
__device__ __forceinline__ void sts4(uint32_t addr, uint32_t v) {
    asm volatile("st.shared.b32 [%0], %1;" :: "r"(addr), "r"(v) : "memory");
}
__device__ __forceinline__ void lds16(uint4& v, uint32_t addr) {
    asm volatile("ld.shared.v4.b32 {%0, %1, %2, %3}, [%4];"
                 : "=r"(v.x), "=r"(v.y), "=r"(v.z), "=r"(v.w) : "r"(addr));
}
__device__ __forceinline__ uint32_t cvt2h(float x0, float x1) {
    __half2 hh = __floats2half2_rn(x0, x1);
    return *(uint32_t*)&hh;
}

// ---------------- A convert (layer 0: gather + convert) ----------------------
__global__ void aconv0_kernel(const int* __restrict__ nodes,
                              const float* __restrict__ emb) {
    int idx = blockIdx.x * blockDim.x + threadIdx.x;   // M_TOT*32
    if (idx >= M_TOT * 32) return;
    int node = idx >> 5;
    int q = idx & 31;
    int v = nodes[node];
    const float4* src = (const float4*)(emb + (size_t)v * D_ + q * 8);
    float4 a = src[0];
    float4 b = src[1];
    uint4 h;
    h.x = cvt2h(a.x, a.y);
    h.y = cvt2h(a.z, a.w);
    h.z = cvt2h(b.x, b.y);
    h.w = cvt2h(b.z, b.w);
    *((uint4*)(g_xh) + idx) = h;
}

// ---------------- CSR build (once; forked stream) ----------------------------
__global__ void zero_counts() {
    int idx = blockIdx.x * blockDim.x + threadIdx.x;
    if (idx < M_TOT) { g_degi[idx] = 0; g_fill[idx] = 0; }
}
// 4 edges per thread (int4)
__global__ void count_deg(const int* __restrict__ edges) {
    int idx = blockIdx.x * blockDim.x + threadIdx.x;   // B_*E_/4
    if (idx >= (B_ * E_) / 4) return;
    int b = idx >> 13;                 // / (E_/4)
    int e4 = idx & ((E_ / 4) - 1);
    const int4 d4 = *(const int4*)(edges + (size_t)b * 2 * E_ + E_ + e4 * 4);
    int base = b * N_;
    atomicAdd(&g_degi[base + d4.x], 1);
    atomicAdd(&g_degi[base + d4.y], 1);
    atomicAdd(&g_degi[base + d4.z], 1);
    atomicAdd(&g_degi[base + d4.w], 1);
}
__global__ void scan1_kernel() {
    __shared__ int ws[8];
    int b = blockIdx.x, t = threadIdx.x, lane = t & 31, w = t >> 5;
    int i = b * 256 + t;
    int d = g_degi[i];
    int v = d;
#pragma unroll
    for (int off = 1; off < 32; off <<= 1) {
        int u = __shfl_up_sync(0xFFFFFFFFu, v, off);
        if (lane >= off) v += u;
    }
    if (lane == 31) ws[w] = v;
    __syncthreads();
    if (w == 0 && lane < 8) {
        int x = ws[lane];
#pragma unroll
        for (int off = 1; off < 8; off <<= 1) {
            int u = __shfl_up_sync(0xFFu, x, off);
            if (lane >= off) x += u;
        }
        ws[lane] = x;
    }
    __syncthreads();
    int incl = v + (w > 0 ? ws[w - 1] : 0);
    g_rowptr[i] = incl - d;
    if (t == 255) g_bsum[b] = incl;
}
__global__ void scan2_kernel() {
    __shared__ int ws[4];
    int t = threadIdx.x, lane = t & 31, w = t >> 5;
    int d = g_bsum[t];
    int v = d;
#pragma unroll
    for (int off = 1; off < 32; off <<= 1) {
        int u = __shfl_up_sync(0xFFFFFFFFu, v, off);
        if (lane >= off) v += u;
    }
    if (lane == 31) ws[w] = v;
    __syncthreads();
    if (w == 0 && lane < 4) {
        int x = ws[lane];
#pragma unroll
        for (int off = 1; off < 4; off <<= 1) {
            int u = __shfl_up_sync(0xFu, x, off);
            if (lane >= off) x += u;
        }
        ws[lane] = x;
    }
    __syncthreads();
    int incl = v + (w > 0 ? ws[w - 1] : 0);
    g_bsum[t] = incl - d;
    if (t == 127) g_rowptr[M_TOT] = incl;
}
__global__ void scan3_kernel() {
    int i = blockIdx.x * blockDim.x + threadIdx.x;
    g_rowptr[i] += g_bsum[blockIdx.x];
}
// 4 edges per thread (int4 src/dst/type)
__global__ void fill_adj(const int* __restrict__ edges,
                         const int* __restrict__ types) {
    int idx = blockIdx.x * blockDim.x + threadIdx.x;   // B_*E_/4
    if (idx >= (B_ * E_) / 4) return;
    int b = idx >> 13;
    int e4 = idx & ((E_ / 4) - 1);
    const int* eb = edges + (size_t)b * 2 * E_;
    const int4 s4 = *(const int4*)(eb + e4 * 4);
    const int4 d4 = *(const int4*)(eb + E_ + e4 * 4);
    const int4 r4 = *(const int4*)(types + (size_t)b * E_ + e4 * 4);
    int base = b * N_;
#pragma unroll
    for (int j = 0; j < 4; j++) {
        int src = (&s4.x)[j];
        int dst = (&d4.x)[j];
        int r = (&r4.x)[j];
        int gdst = base + dst;
        int pos = g_rowptr[gdst] + atomicAdd(&g_fill[gdst], 1);
        g_adj[pos] = (r << 15) | (base + src);
    }
}

// Pre-convert + pre-swizzle W (BOTH layers) into ldmatrix-ready fp16 tiles.
__global__ void bconv_kernel(const float* __restrict__ W,
                             const float* __restrict__ Wroot) {
    int gid = blockIdx.x * blockDim.x + threadIdx.x;   // 2*8*18*512 = 147456
    if (gid >= L_ * NT2 * NBLK * 512) return;
    int tile = gid >> 9;
    int rem = gid & 511;
    int krow = rem >> 4;
    int gq = rem & 15;
    int l = tile / (NT2 * NBLK);
    int t2 = tile - l * (NT2 * NBLK);
    int kt = t2 / NBLK;
    int bx = t2 - kt * NBLK;
    int k = kt * KT2 + krow;
    int n0 = bx * 128 + gq * 8;
    const float* src = (n0 < 2048)
        ? W + (size_t)l * R_ * D_ * D_ + ((size_t)(n0 >> 8) << 16) + (size_t)k * 256 + (n0 & 255)
        : Wroot + (size_t)l * D_ * D_ + (size_t)k * 256 + (n0 - 2048);
    float4 v0 = ((const float4*)src)[0];
    float4 v1 = ((const float4*)src)[1];
    uint4 h;
    h.x = cvt2h(v0.x, v0.y);
    h.y = cvt2h(v0.z, v0.w);
    h.z = cvt2h(v1.x, v1.y);
    h.w = cvt2h(v1.z, v1.w);
    uint32_t off = (uint32_t)tile * 8192u + (uint32_t)krow * 256u +
                   ((uint32_t)(gq ^ (krow & 7)) << 4);
    *(uint4*)(g_Bh + off) = h;
}

// ---------------- atomic-free aggregation (fused epilogue) -------------------
__global__ void __launch_bounds__(256)
aggregate_kernel(const __half* __restrict__ xw, float* __restrict__ Yin,
                 __half* __restrict__ xh_out) {
    int w = (blockIdx.x * blockDim.x + threadIdx.x) >> 5;
    int lane = threadIdx.x & 31;
    if (w >= M_TOT) return;
    int beg = g_rowptr[w];
    int end = g_rowptr[w + 1];

    float acc[8] = {0.f, 0.f, 0.f, 0.f, 0.f, 0.f, 0.f, 0.f};
    int p = beg;
    for (; p + 2 <= end; p += 2) {
        int e0 = g_adj[p];
        int e1 = g_adj[p + 1];
        uint4 v0 = *((const uint4*)(xw + ((size_t)(e0 & 32767) * R_ + (e0 >> 15)) * D_) + lane);
        uint4 v1 = *((const uint4*)(xw + ((size_t)(e1 & 32767) * R_ + (e1 >> 15)) * D_) + lane);
        const __half2* h0 = (const __half2*)&v0;
        const __half2* h1 = (const __half2*)&v1;
#pragma unroll
        for (int j = 0; j < 4; j++) {
            float2 f0 = __half22float2(h0[j]);
            float2 f1 = __half22float2(h1[j]);
            acc[2 * j] += f0.x + f1.x;
            acc[2 * j + 1] += f0.y + f1.y;
        }
    }
    if (p < end) {
        int e0 = g_adj[p];
        uint4 v0 = *((const uint4*)(xw + ((size_t)(e0 & 32767) * R_ + (e0 >> 15)) * D_) + lane);
        const __half2* h0 = (const __half2*)&v0;
#pragma unroll
        for (int j = 0; j < 4; j++) {
            float2 f0 = __half22float2(h0[j]);
            acc[2 * j] += f0.x;
            acc[2 * j + 1] += f0.y;
        }
    }
    float idg = 1.0f / (float)((end - beg) > 1 ? (end - beg) : 1);
    float* yp = Yin + (size_t)w * D_ + lane * 8;
    float4 y0 = *(float4*)yp;
    float4 y1 = *(float4*)(yp + 4);
    y0.x += acc[0] * idg; y0.y += acc[1] * idg;
    y0.z += acc[2] * idg; y0.w += acc[3] * idg;
    y1.x += acc[4] * idg; y1.y += acc[5] * idg;
    y1.z += acc[6] * idg; y1.w += acc[7] * idg;
    if (xh_out) {
        uint4 h;
        h.x = cvt2h(fmaxf(y0.x, 0.f), fmaxf(y0.y, 0.f));
        h.y = cvt2h(fmaxf(y0.z, 0.f), fmaxf(y0.w, 0.f));
        h.z = cvt2h(fmaxf(y1.x, 0.f), fmaxf(y1.y, 0.f));
        h.w = cvt2h(fmaxf(y1.z, 0.f), fmaxf(y1.w, 0.f));
        *((uint4*)(xh_out + (size_t)w * D_) + lane) = h;
    } else {
        *(float4*)yp = y0;
        *(float4*)(yp + 4) = y1;
    }
}

// ---------------- warp-MMA GEMM ----------------------------------------------
// CTA: 128 rows x 128 cols, 256 threads (8 warps: 4M x 2N), 2 CTAs/SM.
// grid (18, 256): bx<16 -> fp16 to XW (smem-staged); bx>=16 -> Y = . + bias
__global__ void __launch_bounds__(256, 2)
rgcn_gemm_mma(const __half* __restrict__ Xh,
              const uint8_t* __restrict__ Bt,
              const float* __restrict__ bias,
              float* __restrict__ Y,
              __half* __restrict__ XW) {
    extern __shared__ uint8_t smem_raw[];
    const uint32_t sbase = (smem_u32(smem_raw) + 127u) & ~127u;

    const int tid = threadIdx.x;
    const int lane = tid & 31;
    const int wid = tid >> 5;
    const int warp_m = wid & 3;
    const int warp_n = wid >> 2;
    const int bx = blockIdx.x;
    const int m0 = blockIdx.y * 128;

    const int arow = tid >> 1;
    const int ac = tid & 1;
    const uint32_t a_sts = (uint32_t)arow * A_STRIDE + (uint32_t)ac * 32;
    const size_t a_goff = (size_t)(m0 + arow) * KDIM + ac * 16;

    const int g = lane >> 2;
    const int tc = lane & 3;

    uint32_t a_off[2];
#pragma unroll
    for (int mt = 0; mt < 2; mt++)
        a_off[mt] = (uint32_t)(warp_m * 32 + mt * 16 + (lane & 15)) * A_STRIDE +
                    (uint32_t)((lane >> 4) * 16);
    const uint32_t krow_base = (uint32_t)((lane & 7) + ((lane >> 3) & 1) * 8);
    uint32_t gg[4];
#pragma unroll
    for (int nt2 = 0; nt2 < 4; nt2++)
        gg[nt2] = (uint32_t)(((warp_n * 8 + nt2 * 2 + (lane >> 4)) ^ (lane & 7)) << 4);

    float c[2][8][4];
#pragma unroll
    for (int mt = 0; mt < 2; mt++)
#pragma unroll
        for (int nt = 0; nt < 8; nt++)
#pragma unroll
            for (int j = 0; j < 4; j++) c[mt][nt][j] = 0.f;

    auto issue_loads = [&](int kt, int s) {
        const uint32_t st = sbase + (uint32_t)s * STAGE;
        const uint8_t* bh = Bt + (size_t)(kt * NBLK + bx) * 8192 + tid * 16;
        cp16(st + OFF_B + tid * 16, bh);
        cp16(st + OFF_B + 4096 + tid * 16, bh + 4096);
        cp16(st + a_sts, Xh + a_goff + kt * KT2);
        cp16(st + a_sts + 16, Xh + a_goff + kt * KT2 + 8);
        asm volatile("cp.async.commit_group;" ::: "memory");
    };

    auto compute = [&](int s) {
        const uint32_t st = sbase + (uint32_t)s * STAGE;
#pragma unroll
        for (int k16 = 0; k16 < 2; k16++) {
            const uint32_t kb2 = (uint32_t)(k16 * 32);
            const uint32_t brow = (uint32_t)((k16 * 16) + krow_base) * 256u;
            uint32_t ah[2][4], bb[4][4];
            ldsm4(ah[0], st + a_off[0] + kb2);
            ldsm4(ah[1], st + a_off[1] + kb2);
#pragma unroll
            for (int nt2 = 0; nt2 < 4; nt2++)
                ldsm4t(bb[nt2], st + OFF_B + brow + gg[nt2]);
#pragma unroll
            for (int mt = 0; mt < 2; mt++)
#pragma unroll
                for (int nt = 0; nt < 8; nt++)
                    mma16816h(c[mt][nt], ah[mt], bb[nt >> 1][(nt & 1) * 2],
                              bb[nt >> 1][(nt & 1) * 2 + 1]);
        }
    };

    issue_loads(0, 0);
    issue_loads(1, 1);
    asm volatile("cp.async.wait_group 1;" ::: "memory");
    __syncthreads();

#pragma unroll 1
    for (int kt = 0; kt < NT2; kt++) {
        const int s = kt % NSTG;
        if (kt + 2 < NT2) issue_loads(kt + 2, (kt + 2) % NSTG);
        compute(s);
        if (kt + 1 < NT2) {
            asm volatile("cp.async.wait_group 1;" ::: "memory");
            __syncthreads();
        }
    }

    if (bx >= 16) {
        const int col0 = (bx - 16) * 128;
#pragma unroll
        for (int mt = 0; mt < 2; mt++) {
            const int row = m0 + warp_m * 32 + mt * 16 + g;
#pragma unroll
            for (int nt = 0; nt < 8; nt++) {
                const int col = col0 + warp_n * 64 + nt * 8 + tc * 2;
                const float b0 = bias[col];
                const float b1 = bias[col + 1];
                *(float2*)&Y[(size_t)row * D_ + col] =
                    make_float2(c[mt][nt][0] + b0, c[mt][nt][1] + b1);
                *(float2*)&Y[(size_t)(row + 8) * D_ + col] =
                    make_float2(c[mt][nt][2] + b0, c[mt][nt][3] + b1);
            }
        }
    } else {
        __syncthreads();
#pragma unroll
        for (int mt = 0; mt < 2; mt++) {
#pragma unroll
            for (int h = 0; h < 2; h++) {
                int lrow = warp_m * 32 + mt * 16 + h * 8 + g;
#pragma unroll
                for (int nt = 0; nt < 8; nt++) {
                    int gran = warp_n * 8 + nt;
                    uint32_t off = (uint32_t)lrow * 256 +
                                   ((uint32_t)(gran ^ (lrow & 7)) << 4) + tc * 4;
                    sts4(sbase + off, cvt2h(c[mt][nt][h * 2], c[mt][nt][h * 2 + 1]));
                }
            }
        }
        __syncthreads();
        __half* dst = XW + (size_t)m0 * (R_ * D_) + bx * 128;
#pragma unroll
        for (int p = 0; p < 8; p++) {
            int i = tid + p * 256;
            int row = i >> 4;
            int gran = i & 15;
            uint32_t soff = (uint32_t)row * 256 +
                            ((uint32_t)(gran ^ (row & 7)) << 4);
            uint4 v;
            lds16(v, sbase + soff);
            *(uint4*)(dst + (size_t)row * (R_ * D_) + gran * 8) = v;
        }
    }
}

// ---------------- launch ----------------------------------------------------
extern "C" void kernel_launch(void* const* d_in, const int* in_sizes, int n_in,
                              void* d_out, int out_size) {
    const int*   nodes = (const int*)d_in[0];
    const int*   edges = (const int*)d_in[1];
    const int*   types = (const int*)d_in[2];
    const float* emb   = (const float*)d_in[3];
    const float* W     = (const float*)d_in[4];
    const float* Wroot = (const float*)d_in[5];
    const float* bias  = (const float*)d_in[6];
    float* out = (float*)d_out;

    // one-time resource setup (first call is the uncaptured correctness run)
    static cudaStream_t s2 = nullptr;
    static cudaEvent_t evFork = nullptr, evJoin = nullptr;
    if (!s2) {
        cudaFuncSetAttribute(rgcn_gemm_mma,
                             cudaFuncAttributeMaxDynamicSharedMemorySize, SMEM_DYN);
        cudaStreamCreateWithFlags(&s2, cudaStreamNonBlocking);
        cudaEventCreateWithFlags(&evFork, cudaEventDisableTiming);
        cudaEventCreateWithFlags(&evJoin, cudaEventDisableTiming);
    }

    float* y0 = nullptr;
    __half *xw = nullptr, *xh = nullptr;
    uint8_t* bh = nullptr;
    cudaGetSymbolAddress((void**)&y0, g_y);
    cudaGetSymbolAddress((void**)&xw, g_xw);
    cudaGetSymbolAddress((void**)&xh, g_xh);
    cudaGetSymbolAddress((void**)&bh, g_Bh);

    // ---- fork: CSR build on s2 (only needed by aggregate_kernel) ----
    cudaEventRecord(evFork, 0);
    cudaStreamWaitEvent(s2, evFork, 0);
    zero_counts<<<M_TOT / 256, 256, 0, s2>>>();
    count_deg<<<(B_ * E_ / 4) / 256, 256, 0, s2>>>(edges);
    scan1_kernel<<<128, 256, 0, s2>>>();
    scan2_kernel<<<1, 128, 0, s2>>>();
    scan3_kernel<<<128, 256, 0, s2>>>();
    fill_adj<<<(B_ * E_ / 4) / 256, 256, 0, s2>>>(edges, types);
    cudaEventRecord(evJoin, s2);

    // ---- main stream: weights + A convert + layer-0 GEMM (overlaps CSR) ----
    bconv_kernel<<<(L_ * NT2 * NBLK * 512) / 256, 256>>>(W, Wroot);
    aconv0_kernel<<<(M_TOT * 32) / 256, 256>>>(nodes, emb);

    dim3 grid(NBLK, M_TOT / 128);   // (18, 256)
    rgcn_gemm_mma<<<grid, 256, SMEM_DYN>>>(xh, bh, bias, y0, xw);

    // join before aggregation needs the CSR
    cudaStreamWaitEvent(0, evJoin, 0);
    aggregate_kernel<<<M_TOT / 8, 256>>>(xw, y0, xh);   // fused relu+fp16 convert

    // layer 1 (final)
    rgcn_gemm_mma<<<grid, 256, SMEM_DYN>>>(xh, bh + (size_t)NT2 * NBLK * 8192,
                                           bias + D_, out, xw);
    aggregate_kernel<<<M_TOT / 8, 256>>>(xw, out, nullptr);
}